// round 3
// baseline (speedup 1.0000x reference)
#include <cuda_runtime.h>
#include <cstdint>
#include <cstddef>

// ---------------------------------------------------------------------------
// Problem dims
// ---------------------------------------------------------------------------
#define Bc 256
#define Tc 256
#define Dc 128
#define Ec 256
#define Hc 256
#define Ac 18

// Output layout: tuple flattened+concatenated in return order.
static constexpr size_t N_LOGITS = (size_t)Bc * Tc * Ac;       // 1,179,648
static constexpr size_t NGATE    = (size_t)Bc * Tc * Hc;       // 16,777,216
static constexpr size_t OFF_LOGITS = 0;
static constexpr size_t OFF_VALUES = OFF_LOGITS + N_LOGITS;
static constexpr size_t OFF_HT     = OFF_VALUES + (size_t)Bc * Tc;
static constexpr size_t OFF_CT     = OFF_HT + (size_t)Bc * Hc;
static constexpr size_t OFF_AR     = OFF_CT + (size_t)Bc * Hc;
static constexpr size_t OFF_TAR    = OFF_AR + 1;
static constexpr size_t OFF_I      = OFF_TAR + 1;
static constexpr size_t OFF_Fg     = OFF_I + NGATE;
static constexpr size_t OFF_Gg     = OFF_Fg + NGATE;
static constexpr size_t OFF_Og     = OFF_Gg + NGATE;
static constexpr size_t OFF_CS     = OFF_Og + NGATE;
static constexpr size_t OFF_HS     = OFF_CS + NGATE;

// ---------------------------------------------------------------------------
// Device scratch (static device globals: allocation-free)
// ---------------------------------------------------------------------------
__device__ float g_enc1[(size_t)Bc * Tc * Ec];        // 64 MB
__device__ float g_enc2[(size_t)Bc * Tc * Ec];        // 64 MB
__device__ float g_pre [(size_t)Bc * Tc * 4 * Hc];    // 256 MB
__device__ float g_bias[4 * Hc];
__device__ float g_part[256];                          // 128 ar + 128 tar partials

// ---------------------------------------------------------------------------
// Math helpers
// ---------------------------------------------------------------------------
__device__ __forceinline__ float sigm(float x) {
    return __fdividef(1.0f, 1.0f + __expf(-x));
}
__device__ __forceinline__ float tanh_f(float x) {
    // 1 - 2/(e^{2x}+1); saturates correctly at +/-inf of expf
    return 1.0f - __fdividef(2.0f, __expf(2.0f * x) + 1.0f);
}
__device__ __forceinline__ float silu(float x) {
    return x * sigm(x);
}

// ---------------------------------------------------------------------------
// Generic GEMM: C[m,n] = act( sum_k A[m,k]*W[n,k] + bias[n] )
// BM=64, BN=64, BK=16, 256 threads, 4x4 per thread. M,N multiples of 64,
// K multiple of 16 (true for all three uses).
// ---------------------------------------------------------------------------
__global__ __launch_bounds__(256)
void gemm_bias_act(const float* __restrict__ A, const float* __restrict__ W,
                   const float* __restrict__ bias, float* __restrict__ C,
                   int K, int N, int act)
{
    __shared__ float As[16][68];
    __shared__ float Ws[16][68];

    const int m0 = blockIdx.x * 64;
    const int n0 = blockIdx.y * 64;
    const int tid = threadIdx.x;
    const int tx = tid & 15;        // 0..15 -> n sub-tile
    const int ty = tid >> 4;        // 0..15 -> m sub-tile
    const int lr = tid >> 2;        // 0..63 load row
    const int ls = tid & 3;         // 0..3  load k-segment

    float acc[4][4] = {};

    for (int k0 = 0; k0 < K; k0 += 16) {
        float4 av = *(const float4*)&A[(size_t)(m0 + lr) * K + k0 + ls * 4];
        float4 wv = *(const float4*)&W[(size_t)(n0 + lr) * K + k0 + ls * 4];
        As[ls * 4 + 0][lr] = av.x; As[ls * 4 + 1][lr] = av.y;
        As[ls * 4 + 2][lr] = av.z; As[ls * 4 + 3][lr] = av.w;
        Ws[ls * 4 + 0][lr] = wv.x; Ws[ls * 4 + 1][lr] = wv.y;
        Ws[ls * 4 + 2][lr] = wv.z; Ws[ls * 4 + 3][lr] = wv.w;
        __syncthreads();
        #pragma unroll
        for (int k = 0; k < 16; ++k) {
            float4 a4 = *(const float4*)&As[k][ty * 4];
            float4 w4 = *(const float4*)&Ws[k][tx * 4];
            float a[4] = {a4.x, a4.y, a4.z, a4.w};
            float w[4] = {w4.x, w4.y, w4.z, w4.w};
            #pragma unroll
            for (int ii = 0; ii < 4; ++ii)
                #pragma unroll
                for (int jj = 0; jj < 4; ++jj)
                    acc[ii][jj] = fmaf(a[ii], w[jj], acc[ii][jj]);
        }
        __syncthreads();
    }

    const int nbase = n0 + tx * 4;
    float b0 = bias[nbase + 0], b1 = bias[nbase + 1];
    float b2 = bias[nbase + 2], b3 = bias[nbase + 3];
    #pragma unroll
    for (int ii = 0; ii < 4; ++ii) {
        const int m = m0 + ty * 4 + ii;
        float4 r;
        r.x = acc[ii][0] + b0; r.y = acc[ii][1] + b1;
        r.z = acc[ii][2] + b2; r.w = acc[ii][3] + b3;
        if (act) { r.x = silu(r.x); r.y = silu(r.y); r.z = silu(r.z); r.w = silu(r.w); }
        *(float4*)&C[(size_t)m * N + nbase] = r;
    }
}

// ---------------------------------------------------------------------------
// bias prep: g_bias = b_ih + b_hh
// ---------------------------------------------------------------------------
__global__ void prep_bias(const float* __restrict__ bih, const float* __restrict__ bhh)
{
    int i = threadIdx.x;            // blockDim = 1024
    g_bias[i] = bih[i] + bhh[i];
}

// ---------------------------------------------------------------------------
// Persistent cluster LSTM.
// Grid = 128 CTAs of 128 threads, clusters of 8.
//   cluster g owns batch rows [16g, 16g+16)
//   rank r owns hidden units [32r, 32r+32)  (w_hh slice 128x256 in SMEM)
// Per step: gates = pre[b,t,:] + h @ w_hh_slice^T, pointwise LSTM cell,
// DSMEM-push own h chunk to all 8 ranks (double-buffered), cluster.sync.
// Thread map: j = tid&31 (unit), s = tid>>5 (warp); rows {s, s+4, s+8, s+12}.
// ---------------------------------------------------------------------------
__device__ __forceinline__ void push_h8(unsigned laddr, float v)
{
    #pragma unroll
    for (int rk = 0; rk < 8; ++rk) {
        unsigned ra;
        asm volatile("mapa.shared::cluster.u32 %0, %1, %2;" : "=r"(ra) : "r"(laddr), "r"(rk));
        asm volatile("st.shared::cluster.f32 [%0], %1;" :: "r"(ra), "f"(v));
    }
}
__device__ __forceinline__ void cluster_sync_()
{
    asm volatile("barrier.cluster.arrive.aligned;" ::: "memory");
    asm volatile("barrier.cluster.wait.aligned;"   ::: "memory");
}

#define WSH_STRIDE 260   // 256 + 4 pad: conflict-free LDS.128 across j
#define LSTM_SMEM (128 * WSH_STRIDE * 4 + 2 * 16 * 256 * 4)   // 133120 + 32768

__global__ void __cluster_dims__(8, 1, 1) __launch_bounds__(128, 1)
lstm_kernel(const float* __restrict__ hxs, const float* __restrict__ cxs,
            const float* __restrict__ w_hh, float* __restrict__ out)
{
    extern __shared__ float smem[];
    float* wsh = smem;                            // [128][WSH_STRIDE]
    float* hb0 = smem + 128 * WSH_STRIDE;         // [16][256]
    float* hb1 = hb0 + 16 * 256;                  // [16][256]

    const int tid  = threadIdx.x;
    const int grp  = blockIdx.x >> 3;
    const int rank = blockIdx.x & 7;
    const int b0   = grp * 16;
    const int u0   = rank * 32;
    const int j    = tid & 31;
    const int s    = tid >> 5;                    // warp id 0..3

    // ---- load w_hh slice: gate rows {q*256+u0+j'} for q=0..3, j'=0..31 ----
    for (int idx = tid; idx < 128 * 64; idx += 128) {
        int rr = idx >> 6;                        // 0..127 = q*32 + jj
        int k4 = idx & 63;
        int q = rr >> 5, jj = rr & 31;
        float4 v = *(const float4*)&w_hh[(size_t)((q << 8) + u0 + jj) * Hc + (k4 << 2)];
        *(float4*)&wsh[rr * WSH_STRIDE + (k4 << 2)] = v;
    }
    // ---- init h buffer 0 from hxs (full 16x256 rows, no exchange needed) ----
    for (int idx = tid; idx < 16 * 64; idx += 128) {
        int row = idx >> 6, k4 = idx & 63;
        *(float4*)&hb0[row * 256 + (k4 << 2)] =
            *(const float4*)&hxs[(size_t)(b0 + row) * Hc + (k4 << 2)];
    }

    int   gr[4]; int ro[4];
    float c[4], hp[4];
    #pragma unroll
    for (int i = 0; i < 4; ++i) {
        int row = s + 4 * i;
        gr[i] = b0 + row;
        ro[i] = row * 256;
        c[i]  = cxs[(size_t)gr[i] * Hc + u0 + j];
        hp[i] = 0.0f;
    }
    float ar = 0.0f, tar = 0.0f;
    __syncthreads();

    const float* w0 = &wsh[(0 * 32 + j) * WSH_STRIDE];
    const float* w1 = &wsh[(1 * 32 + j) * WSH_STRIDE];
    const float* w2 = &wsh[(2 * 32 + j) * WSH_STRIDE];
    const float* w3 = &wsh[(3 * 32 + j) * WSH_STRIDE];

    int cur = 0;
    for (int t = 0; t < Tc; ++t) {
        const float* hc = cur ? hb1 : hb0;
        float*       hn = cur ? hb0 : hb1;

        float acc[4][4];
        #pragma unroll
        for (int i = 0; i < 4; ++i) {
            const float* pr = &g_pre[(size_t)(gr[i] * Tc + t) * (4 * Hc) + u0 + j];
            acc[i][0] = pr[0];   acc[i][1] = pr[256];
            acc[i][2] = pr[512]; acc[i][3] = pr[768];
        }

        #pragma unroll 4
        for (int k4 = 0; k4 < 64; ++k4) {
            const int k = k4 << 2;
            float4 a = *(const float4*)&w0[k];
            float4 b = *(const float4*)&w1[k];
            float4 g = *(const float4*)&w2[k];
            float4 o = *(const float4*)&w3[k];
            #pragma unroll
            for (int i = 0; i < 4; ++i) {
                float4 h4 = *(const float4*)&hc[ro[i] + k];   // warp-broadcast
                acc[i][0] = fmaf(h4.x, a.x, acc[i][0]);
                acc[i][0] = fmaf(h4.y, a.y, acc[i][0]);
                acc[i][0] = fmaf(h4.z, a.z, acc[i][0]);
                acc[i][0] = fmaf(h4.w, a.w, acc[i][0]);
                acc[i][1] = fmaf(h4.x, b.x, acc[i][1]);
                acc[i][1] = fmaf(h4.y, b.y, acc[i][1]);
                acc[i][1] = fmaf(h4.z, b.z, acc[i][1]);
                acc[i][1] = fmaf(h4.w, b.w, acc[i][1]);
                acc[i][2] = fmaf(h4.x, g.x, acc[i][2]);
                acc[i][2] = fmaf(h4.y, g.y, acc[i][2]);
                acc[i][2] = fmaf(h4.z, g.z, acc[i][2]);
                acc[i][2] = fmaf(h4.w, g.w, acc[i][2]);
                acc[i][3] = fmaf(h4.x, o.x, acc[i][3]);
                acc[i][3] = fmaf(h4.y, o.y, acc[i][3]);
                acc[i][3] = fmaf(h4.z, o.z, acc[i][3]);
                acc[i][3] = fmaf(h4.w, o.w, acc[i][3]);
            }
        }

        #pragma unroll
        for (int i = 0; i < 4; ++i) {
            float iv = sigm(acc[i][0]);
            float fv = sigm(acc[i][1]);
            float gv = tanh_f(acc[i][2]);
            float ov = sigm(acc[i][3]);
            float c2 = fmaf(fv, c[i], iv * gv);
            float h2 = ov * tanh_f(c2);
            c[i] = c2;
            ar = fmaf(h2, h2, ar);
            float d = h2 - hp[i];
            if (t > 0) tar = fmaf(d, d, tar);
            hp[i] = h2;

            const size_t base = (size_t)(gr[i] * Tc + t) * Hc + u0 + j;
            __stcs(&out[OFF_I  + base], iv);
            __stcs(&out[OFF_Fg + base], fv);
            __stcs(&out[OFF_Gg + base], gv);
            __stcs(&out[OFF_Og + base], ov);
            __stcs(&out[OFF_CS + base], c2);
            __stcs(&out[OFF_HS + base], h2);
            if (t == Tc - 1) {
                out[OFF_HT + (size_t)gr[i] * Hc + u0 + j] = h2;
                out[OFF_CT + (size_t)gr[i] * Hc + u0 + j] = c2;
            }
            unsigned laddr = (unsigned)__cvta_generic_to_shared(&hn[ro[i] + u0 + j]);
            push_h8(laddr, h2);
        }

        cluster_sync_();
        cur ^= 1;
    }

    // ---- loss partial reduce (per CTA) ----
    __shared__ float red[128];
    red[tid] = ar; __syncthreads();
    for (int o = 64; o > 0; o >>= 1) { if (tid < o) red[tid] += red[tid + o]; __syncthreads(); }
    if (tid == 0) g_part[blockIdx.x] = red[0];
    __syncthreads();
    red[tid] = tar; __syncthreads();
    for (int o = 64; o > 0; o >>= 1) { if (tid < o) red[tid] += red[tid + o]; __syncthreads(); }
    if (tid == 0) g_part[128 + blockIdx.x] = red[0];
}

// ---------------------------------------------------------------------------
// loss finalize
// ---------------------------------------------------------------------------
__global__ void loss_fin(float* __restrict__ out)
{
    __shared__ float r[128];
    int tid = threadIdx.x;
    r[tid] = g_part[tid]; __syncthreads();
    for (int o = 64; o > 0; o >>= 1) { if (tid < o) r[tid] += r[tid + o]; __syncthreads(); }
    float sar = r[0]; __syncthreads();
    r[tid] = g_part[128 + tid]; __syncthreads();
    for (int o = 64; o > 0; o >>= 1) { if (tid < o) r[tid] += r[tid + o]; __syncthreads(); }
    if (tid == 0) {
        out[OFF_AR]  = sar * (0.01f / 16777216.0f);   // mean over B*T*H
        out[OFF_TAR] = r[0] * (0.01f / 16711680.0f);  // mean over B*(T-1)*H
    }
}

// ---------------------------------------------------------------------------
// actor/critic heads: logits = hs @ actor_w^T + b, values = hs @ critic_w^T + b
// warp per (b,t) row; 8 rows per block.
// ---------------------------------------------------------------------------
__global__ __launch_bounds__(256)
void head_kernel(const float* __restrict__ aw, const float* __restrict__ ab,
                 const float* __restrict__ cw, const float* __restrict__ cb,
                 float* __restrict__ out)
{
    __shared__ float ws[19 * 256];
    const int tid = threadIdx.x;
    for (int i = tid; i < Ac * Hc; i += 256) ws[i] = aw[i];
    for (int i = tid; i < Hc; i += 256) ws[Ac * Hc + i] = cw[i];
    __syncthreads();

    const int warp = tid >> 5, lane = tid & 31;
    const size_t m = (size_t)blockIdx.x * 8 + warp;           // 0..65535
    const float* h = &out[OFF_HS + m * Hc];

    float p[19];
    #pragma unroll
    for (int o = 0; o < 19; ++o) p[o] = 0.0f;
    #pragma unroll
    for (int kk = 0; kk < 8; ++kk) {
        int k = lane + kk * 32;
        float hv = h[k];
        #pragma unroll
        for (int o = 0; o < 19; ++o) p[o] = fmaf(hv, ws[o * 256 + k], p[o]);
    }
    #pragma unroll
    for (int o = 0; o < 19; ++o)
        #pragma unroll
        for (int off = 16; off > 0; off >>= 1)
            p[o] += __shfl_down_sync(0xffffffffu, p[o], off);

    if (lane == 0) {
        #pragma unroll
        for (int o = 0; o < Ac; ++o)
            out[OFF_LOGITS + m * Ac + o] = p[o] + ab[o];
        out[OFF_VALUES + m] = p[18] + cb[0];
    }
}

// ---------------------------------------------------------------------------
// launcher
// ---------------------------------------------------------------------------
extern "C" void kernel_launch(void* const* d_in, const int* in_sizes, int n_in,
                              void* d_out, int out_size)
{
    const float* obs    = (const float*)d_in[0];
    const float* hxs    = (const float*)d_in[1];
    const float* cxs    = (const float*)d_in[2];
    const float* enc_w1 = (const float*)d_in[3];
    const float* enc_b1 = (const float*)d_in[4];
    const float* enc_w2 = (const float*)d_in[5];
    const float* enc_b2 = (const float*)d_in[6];
    const float* w_ih   = (const float*)d_in[7];
    const float* w_hh   = (const float*)d_in[8];
    const float* b_ih   = (const float*)d_in[9];
    const float* b_hh   = (const float*)d_in[10];
    const float* aw     = (const float*)d_in[11];
    const float* ab     = (const float*)d_in[12];
    const float* cw     = (const float*)d_in[13];
    const float* cb     = (const float*)d_in[14];
    float* out = (float*)d_out;

    void *p_enc1, *p_enc2, *p_pre, *p_bias;
    cudaGetSymbolAddress(&p_enc1, g_enc1);
    cudaGetSymbolAddress(&p_enc2, g_enc2);
    cudaGetSymbolAddress(&p_pre,  g_pre);
    cudaGetSymbolAddress(&p_bias, g_bias);

    cudaFuncSetAttribute(lstm_kernel,
                         cudaFuncAttributeMaxDynamicSharedMemorySize, LSTM_SMEM);

    const int M = Bc * Tc;  // 65536

    prep_bias<<<1, 1024>>>(b_ih, b_hh);
    // enc1 = silu(obs @ w1^T + b1):  M x 256, K=128
    gemm_bias_act<<<dim3(M / 64, Ec / 64), 256>>>(obs, enc_w1, enc_b1,
                                                  (float*)p_enc1, Dc, Ec, 1);
    // enc2 = silu(enc1 @ w2^T + b2): M x 256, K=256
    gemm_bias_act<<<dim3(M / 64, Ec / 64), 256>>>((const float*)p_enc1, enc_w2, enc_b2,
                                                  (float*)p_enc2, Ec, Ec, 1);
    // pre = enc2 @ w_ih^T + (b_ih+b_hh): M x 1024, K=256
    gemm_bias_act<<<dim3(M / 64, (4 * Hc) / 64), 256>>>((const float*)p_enc2, w_ih,
                                                        (const float*)p_bias,
                                                        (float*)p_pre, Ec, 4 * Hc, 0);
    // persistent cluster LSTM
    lstm_kernel<<<128, 128, LSTM_SMEM>>>(hxs, cxs, w_hh, out);
    // losses
    loss_fin<<<1, 128>>>(out);
    // heads (reads hs region of out)
    head_kernel<<<M / 8, 256>>>(aw, ab, cw, cb, out);
}

// round 6
// speedup vs baseline: 1.2081x; 1.2081x over previous
#include <cuda_runtime.h>
#include <cuda_bf16.h>
#include <cstdint>
#include <cstddef>

// ---------------------------------------------------------------------------
// Problem dims
// ---------------------------------------------------------------------------
#define Bc 256
#define Tc 256
#define Dc 128
#define Ec 256
#define Hc 256
#define Ac 18

// Output layout: tuple flattened+concatenated in return order.
static constexpr size_t N_LOGITS = (size_t)Bc * Tc * Ac;
static constexpr size_t NGATE    = (size_t)Bc * Tc * Hc;
static constexpr size_t OFF_LOGITS = 0;
static constexpr size_t OFF_VALUES = OFF_LOGITS + N_LOGITS;
static constexpr size_t OFF_HT     = OFF_VALUES + (size_t)Bc * Tc;
static constexpr size_t OFF_CT     = OFF_HT + (size_t)Bc * Hc;
static constexpr size_t OFF_AR     = OFF_CT + (size_t)Bc * Hc;
static constexpr size_t OFF_TAR    = OFF_AR + 1;
static constexpr size_t OFF_I      = OFF_TAR + 1;
static constexpr size_t OFF_Fg     = OFF_I + NGATE;
static constexpr size_t OFF_Gg     = OFF_Fg + NGATE;
static constexpr size_t OFF_Og     = OFF_Gg + NGATE;
static constexpr size_t OFF_CS     = OFF_Og + NGATE;
static constexpr size_t OFF_HS     = OFF_CS + NGATE;

// ---------------------------------------------------------------------------
// Device scratch (static device globals: allocation-free)
// ---------------------------------------------------------------------------
__device__ float         g_pre [(size_t)Bc * Tc * 4 * Hc];    // 256 MB
__device__ float         g_bias[4 * Hc];
__device__ float         g_part[256];
// split-bf16 planes
__device__ __nv_bfloat16 g_obs_h[(size_t)Bc * Tc * Dc];
__device__ __nv_bfloat16 g_obs_l[(size_t)Bc * Tc * Dc];
__device__ __nv_bfloat16 g_e1h[(size_t)Bc * Tc * Ec];
__device__ __nv_bfloat16 g_e1l[(size_t)Bc * Tc * Ec];
__device__ __nv_bfloat16 g_e2h[(size_t)Bc * Tc * Ec];
__device__ __nv_bfloat16 g_e2l[(size_t)Bc * Tc * Ec];
__device__ __nv_bfloat16 g_w1h[Ec * Dc],      g_w1l[Ec * Dc];
__device__ __nv_bfloat16 g_w2h[Ec * Ec],      g_w2l[Ec * Ec];
__device__ __nv_bfloat16 g_wih_h[4 * Hc * Ec], g_wih_l[4 * Hc * Ec];

// single dynamic-shared declaration (used by lstm_kernel only)
extern __shared__ __align__(1024) char dynsmem[];

// ---------------------------------------------------------------------------
// Math helpers
// ---------------------------------------------------------------------------
__device__ __forceinline__ float sigm(float x) {
    return __fdividef(1.0f, 1.0f + __expf(-x));
}
__device__ __forceinline__ float tanh_f(float x) {
    return 1.0f - __fdividef(2.0f, __expf(2.0f * x) + 1.0f);
}
__device__ __forceinline__ float silu(float x) { return x * sigm(x); }

__device__ __forceinline__ uint32_t smem_u32(const void* p) {
    uint32_t a;
    asm("{ .reg .u64 t; cvta.to.shared.u64 t, %1; cvt.u32.u64 %0, t; }" : "=r"(a) : "l"(p));
    return a;
}

// ---------------------------------------------------------------------------
// warp-MMA primitives (baseline PTX: sm_80+ / sm_75+, valid at target sm_100)
// ---------------------------------------------------------------------------
__device__ __forceinline__ void ldsm4(uint32_t* r, uint32_t addr) {
    asm volatile("ldmatrix.sync.aligned.m8n8.x4.shared.b16 {%0,%1,%2,%3}, [%4];"
                 : "=r"(r[0]), "=r"(r[1]), "=r"(r[2]), "=r"(r[3]) : "r"(addr));
}
__device__ __forceinline__ void ldsm2(uint32_t* r, uint32_t addr) {
    asm volatile("ldmatrix.sync.aligned.m8n8.x2.shared.b16 {%0,%1}, [%2];"
                 : "=r"(r[0]), "=r"(r[1]) : "r"(addr));
}
__device__ __forceinline__ void mma16816(float* d, const uint32_t* a, const uint32_t* b) {
    asm volatile("mma.sync.aligned.m16n8k16.row.col.f32.bf16.bf16.f32 "
                 "{%0,%1,%2,%3}, {%4,%5,%6,%7}, {%8,%9}, {%0,%1,%2,%3};"
                 : "+f"(d[0]), "+f"(d[1]), "+f"(d[2]), "+f"(d[3])
                 : "r"(a[0]), "r"(a[1]), "r"(a[2]), "r"(a[3]), "r"(b[0]), "r"(b[1]));
}

// ---------------------------------------------------------------------------
// fp32 -> (hi, lo) bf16 split
// ---------------------------------------------------------------------------
__global__ void conv_split(const float* __restrict__ in, __nv_bfloat16* __restrict__ h,
                           __nv_bfloat16* __restrict__ l, int n)
{
    int i = blockIdx.x * blockDim.x + threadIdx.x;
    if (i >= n) return;
    float x = in[i];
    __nv_bfloat16 hb = __float2bfloat16(x);
    h[i] = hb;
    l[i] = __float2bfloat16(x - __bfloat162float(hb));
}

// ---------------------------------------------------------------------------
// split-bf16 tensor-core GEMM: D[m,n] = sum_k A[m,k]*W[n,k]  (fp32 accum)
// 3 passes: Ah*Bh + Al*Bh + Ah*Bl.
// CTA tile 128x64, 8 warps (4 m x 2 n), warp tile 32x32, BK=32.
// mode 0: outF = D + bias[n];  mode 1: silu(D+bias) -> bf16 hi/lo planes.
// SMEM rows padded to 40 bf16 (80B): conflict-free ldmatrix.
// ---------------------------------------------------------------------------
#define ASTR 40   // bf16 elements per smem row (32 data + 8 pad)

__global__ __launch_bounds__(256)
void gemm_mma(const __nv_bfloat16* __restrict__ Ah, const __nv_bfloat16* __restrict__ Al,
              const __nv_bfloat16* __restrict__ Wh, const __nv_bfloat16* __restrict__ Wl,
              const float* __restrict__ bias, float* __restrict__ outF,
              __nv_bfloat16* __restrict__ outH, __nv_bfloat16* __restrict__ outL,
              int K, int N, int mode)
{
    __shared__ float sbias[64];
    __shared__ __align__(16) __nv_bfloat16 sAh[128 * ASTR];
    __shared__ __align__(16) __nv_bfloat16 sAl[128 * ASTR];
    __shared__ __align__(16) __nv_bfloat16 sBh[64 * ASTR];
    __shared__ __align__(16) __nv_bfloat16 sBl[64 * ASTR];

    const int tid  = threadIdx.x;
    const int lane = tid & 31;
    const int w    = tid >> 5;
    const int wm   = w & 3;          // warp m index (0..3) -> rows wm*32
    const int wn   = w >> 2;         // warp n index (0..1) -> cols wn*32
    const int m0   = blockIdx.x * 128;
    const int n0   = blockIdx.y * 64;

    if (tid < 64) sbias[tid] = bias[n0 + tid];

    // lane-dependent ldmatrix source offsets
    const int aro = (lane & 7) + ((lane >> 3) & 1) * 8;   // row within 16
    const int ac16 = (lane >> 4) & 1;                     // k8 half (bytes/16)
    const int bl8 = lane & 15;
    const int bro = bl8 & 7;
    const int bc16 = (bl8 >> 3) & 1;

    const uint32_t uAh = smem_u32(sAh), uAl = smem_u32(sAl);
    const uint32_t uBh = smem_u32(sBh), uBl = smem_u32(sBl);

    // per-thread ldmatrix base addresses (add mt*16*80 / nt*8*80 / ks*32)
    const uint32_t aOffA = (uint32_t)(wm * 32 + aro) * (ASTR * 2) + ac16 * 16;
    const uint32_t aOffB = (uint32_t)(wn * 32 + bro) * (ASTR * 2) + bc16 * 16;

    float acc[2][4][4];
    #pragma unroll
    for (int mt = 0; mt < 2; ++mt)
        #pragma unroll
        for (int nt = 0; nt < 4; ++nt)
            #pragma unroll
            for (int r = 0; r < 4; ++r) acc[mt][nt][r] = 0.0f;

    for (int k0 = 0; k0 < K; k0 += 32) {
        // global -> smem (hi & lo planes)
        #pragma unroll
        for (int i = 0; i < 2; ++i) {
            int idx = tid + (i << 8);
            int row = idx >> 2, ch = idx & 3;
            size_t g = (size_t)(m0 + row) * K + k0 + ch * 8;
            *(uint4*)((char*)sAh + row * (ASTR * 2) + ch * 16) = *(const uint4*)(Ah + g);
            *(uint4*)((char*)sAl + row * (ASTR * 2) + ch * 16) = *(const uint4*)(Al + g);
        }
        {
            int row = tid >> 2, ch = tid & 3;
            size_t g = (size_t)(n0 + row) * K + k0 + ch * 8;
            *(uint4*)((char*)sBh + row * (ASTR * 2) + ch * 16) = *(const uint4*)(Wh + g);
            *(uint4*)((char*)sBl + row * (ASTR * 2) + ch * 16) = *(const uint4*)(Wl + g);
        }
        __syncthreads();

        #pragma unroll
        for (int ks = 0; ks < 2; ++ks) {
            uint32_t ah[2][4], al[2][4], bh[4][2], bl[4][2];
            #pragma unroll
            for (int mt = 0; mt < 2; ++mt) {
                uint32_t o = aOffA + (uint32_t)mt * 16 * (ASTR * 2) + ks * 32;
                ldsm4(ah[mt], uAh + o);
                ldsm4(al[mt], uAl + o);
            }
            #pragma unroll
            for (int nt = 0; nt < 4; ++nt) {
                uint32_t o = aOffB + (uint32_t)nt * 8 * (ASTR * 2) + ks * 32;
                ldsm2(bh[nt], uBh + o);
                ldsm2(bl[nt], uBl + o);
            }
            #pragma unroll
            for (int mt = 0; mt < 2; ++mt)
                #pragma unroll
                for (int nt = 0; nt < 4; ++nt) {
                    mma16816(acc[mt][nt], ah[mt], bh[nt]);
                    mma16816(acc[mt][nt], al[mt], bh[nt]);
                    mma16816(acc[mt][nt], ah[mt], bl[nt]);
                }
        }
        __syncthreads();
    }

    // epilogue
    const int colw = wn * 32;
    #pragma unroll
    for (int mt = 0; mt < 2; ++mt) {
        const int r0 = m0 + wm * 32 + mt * 16 + (lane >> 2);
        #pragma unroll
        for (int nt = 0; nt < 4; ++nt) {
            const int cl = colw + nt * 8 + (lane & 3) * 2;  // local col within 64
            const int c  = n0 + cl;
            float v0 = acc[mt][nt][0] + sbias[cl];
            float v1 = acc[mt][nt][1] + sbias[cl + 1];
            float v2 = acc[mt][nt][2] + sbias[cl];
            float v3 = acc[mt][nt][3] + sbias[cl + 1];
            if (mode == 0) {
                *(float2*)&outF[(size_t)r0 * N + c]       = make_float2(v0, v1);
                *(float2*)&outF[(size_t)(r0 + 8) * N + c] = make_float2(v2, v3);
            } else {
                v0 = silu(v0); v1 = silu(v1); v2 = silu(v2); v3 = silu(v3);
                __nv_bfloat16 h0 = __float2bfloat16(v0), h1 = __float2bfloat16(v1);
                __nv_bfloat16 h2 = __float2bfloat16(v2), h3 = __float2bfloat16(v3);
                __nv_bfloat16 l0 = __float2bfloat16(v0 - __bfloat162float(h0));
                __nv_bfloat16 l1 = __float2bfloat16(v1 - __bfloat162float(h1));
                __nv_bfloat16 l2 = __float2bfloat16(v2 - __bfloat162float(h2));
                __nv_bfloat16 l3 = __float2bfloat16(v3 - __bfloat162float(h3));
                size_t o0 = (size_t)r0 * N + c, o1 = (size_t)(r0 + 8) * N + c;
                *(__nv_bfloat162*)&outH[o0] = __nv_bfloat162(h0, h1);
                *(__nv_bfloat162*)&outL[o0] = __nv_bfloat162(l0, l1);
                *(__nv_bfloat162*)&outH[o1] = __nv_bfloat162(h2, h3);
                *(__nv_bfloat162*)&outL[o1] = __nv_bfloat162(l2, l3);
            }
        }
    }
}

// ---------------------------------------------------------------------------
// bias prep: g_bias = b_ih + b_hh
// ---------------------------------------------------------------------------
__global__ void prep_bias(const float* __restrict__ bih, const float* __restrict__ bhh)
{
    int i = threadIdx.x;
    g_bias[i] = bih[i] + bhh[i];
}

// ---------------------------------------------------------------------------
// Persistent cluster LSTM (proven in R2)
// ---------------------------------------------------------------------------
__device__ __forceinline__ void push_h8(unsigned laddr, float v)
{
    #pragma unroll
    for (int rk = 0; rk < 8; ++rk) {
        unsigned ra;
        asm volatile("mapa.shared::cluster.u32 %0, %1, %2;" : "=r"(ra) : "r"(laddr), "r"(rk));
        asm volatile("st.shared::cluster.f32 [%0], %1;" :: "r"(ra), "f"(v));
    }
}
__device__ __forceinline__ void cluster_sync_()
{
    asm volatile("barrier.cluster.arrive.aligned;" ::: "memory");
    asm volatile("barrier.cluster.wait.aligned;"   ::: "memory");
}

#define WSH_STRIDE 260
#define LSTM_SMEM (128 * WSH_STRIDE * 4 + 2 * 16 * 256 * 4)

__global__ void __cluster_dims__(8, 1, 1) __launch_bounds__(128, 1)
lstm_kernel(const float* __restrict__ hxs, const float* __restrict__ cxs,
            const float* __restrict__ w_hh, float* __restrict__ out)
{
    float* smem = (float*)dynsmem;
    float* wsh = smem;
    float* hb0 = smem + 128 * WSH_STRIDE;
    float* hb1 = hb0 + 16 * 256;

    const int tid  = threadIdx.x;
    const int grp  = blockIdx.x >> 3;
    const int rank = blockIdx.x & 7;
    const int b0   = grp * 16;
    const int u0   = rank * 32;
    const int j    = tid & 31;
    const int s    = tid >> 5;

    for (int idx = tid; idx < 128 * 64; idx += 128) {
        int rr = idx >> 6;
        int k4 = idx & 63;
        int q = rr >> 5, jj = rr & 31;
        float4 v = *(const float4*)&w_hh[(size_t)((q << 8) + u0 + jj) * Hc + (k4 << 2)];
        *(float4*)&wsh[rr * WSH_STRIDE + (k4 << 2)] = v;
    }
    for (int idx = tid; idx < 16 * 64; idx += 128) {
        int row = idx >> 6, k4 = idx & 63;
        *(float4*)&hb0[row * 256 + (k4 << 2)] =
            *(const float4*)&hxs[(size_t)(b0 + row) * Hc + (k4 << 2)];
    }

    int   gr[4]; int ro[4];
    float c[4], hp[4];
    #pragma unroll
    for (int i = 0; i < 4; ++i) {
        int row = s + 4 * i;
        gr[i] = b0 + row;
        ro[i] = row * 256;
        c[i]  = cxs[(size_t)gr[i] * Hc + u0 + j];
        hp[i] = 0.0f;
    }
    float ar = 0.0f, tar = 0.0f;
    __syncthreads();

    const float* w0 = &wsh[(0 * 32 + j) * WSH_STRIDE];
    const float* w1 = &wsh[(1 * 32 + j) * WSH_STRIDE];
    const float* w2 = &wsh[(2 * 32 + j) * WSH_STRIDE];
    const float* w3 = &wsh[(3 * 32 + j) * WSH_STRIDE];

    int cur = 0;
    for (int t = 0; t < Tc; ++t) {
        const float* hc = cur ? hb1 : hb0;
        float*       hn = cur ? hb0 : hb1;

        float acc[4][4];
        #pragma unroll
        for (int i = 0; i < 4; ++i) {
            const float* pr = &g_pre[(size_t)(gr[i] * Tc + t) * (4 * Hc) + u0 + j];
            acc[i][0] = pr[0];   acc[i][1] = pr[256];
            acc[i][2] = pr[512]; acc[i][3] = pr[768];
        }

        #pragma unroll 4
        for (int k4 = 0; k4 < 64; ++k4) {
            const int k = k4 << 2;
            float4 a = *(const float4*)&w0[k];
            float4 b = *(const float4*)&w1[k];
            float4 g = *(const float4*)&w2[k];
            float4 o = *(const float4*)&w3[k];
            #pragma unroll
            for (int i = 0; i < 4; ++i) {
                float4 h4 = *(const float4*)&hc[ro[i] + k];
                acc[i][0] = fmaf(h4.x, a.x, acc[i][0]);
                acc[i][0] = fmaf(h4.y, a.y, acc[i][0]);
                acc[i][0] = fmaf(h4.z, a.z, acc[i][0]);
                acc[i][0] = fmaf(h4.w, a.w, acc[i][0]);
                acc[i][1] = fmaf(h4.x, b.x, acc[i][1]);
                acc[i][1] = fmaf(h4.y, b.y, acc[i][1]);
                acc[i][1] = fmaf(h4.z, b.z, acc[i][1]);
                acc[i][1] = fmaf(h4.w, b.w, acc[i][1]);
                acc[i][2] = fmaf(h4.x, g.x, acc[i][2]);
                acc[i][2] = fmaf(h4.y, g.y, acc[i][2]);
                acc[i][2] = fmaf(h4.z, g.z, acc[i][2]);
                acc[i][2] = fmaf(h4.w, g.w, acc[i][2]);
                acc[i][3] = fmaf(h4.x, o.x, acc[i][3]);
                acc[i][3] = fmaf(h4.y, o.y, acc[i][3]);
                acc[i][3] = fmaf(h4.z, o.z, acc[i][3]);
                acc[i][3] = fmaf(h4.w, o.w, acc[i][3]);
            }
        }

        #pragma unroll
        for (int i = 0; i < 4; ++i) {
            float iv = sigm(acc[i][0]);
            float fv = sigm(acc[i][1]);
            float gv = tanh_f(acc[i][2]);
            float ov = sigm(acc[i][3]);
            float c2 = fmaf(fv, c[i], iv * gv);
            float h2 = ov * tanh_f(c2);
            c[i] = c2;
            ar = fmaf(h2, h2, ar);
            float d = h2 - hp[i];
            if (t > 0) tar = fmaf(d, d, tar);
            hp[i] = h2;

            const size_t base = (size_t)(gr[i] * Tc + t) * Hc + u0 + j;
            __stcs(&out[OFF_I  + base], iv);
            __stcs(&out[OFF_Fg + base], fv);
            __stcs(&out[OFF_Gg + base], gv);
            __stcs(&out[OFF_Og + base], ov);
            __stcs(&out[OFF_CS + base], c2);
            __stcs(&out[OFF_HS + base], h2);
            if (t == Tc - 1) {
                out[OFF_HT + (size_t)gr[i] * Hc + u0 + j] = h2;
                out[OFF_CT + (size_t)gr[i] * Hc + u0 + j] = c2;
            }
            unsigned laddr = (unsigned)__cvta_generic_to_shared(&hn[ro[i] + u0 + j]);
            push_h8(laddr, h2);
        }

        cluster_sync_();
        cur ^= 1;
    }

    __shared__ float red[128];
    red[tid] = ar; __syncthreads();
    for (int o = 64; o > 0; o >>= 1) { if (tid < o) red[tid] += red[tid + o]; __syncthreads(); }
    if (tid == 0) g_part[blockIdx.x] = red[0];
    __syncthreads();
    red[tid] = tar; __syncthreads();
    for (int o = 64; o > 0; o >>= 1) { if (tid < o) red[tid] += red[tid + o]; __syncthreads(); }
    if (tid == 0) g_part[128 + blockIdx.x] = red[0];
}

// ---------------------------------------------------------------------------
// loss finalize
// ---------------------------------------------------------------------------
__global__ void loss_fin(float* __restrict__ out)
{
    __shared__ float r[128];
    int tid = threadIdx.x;
    r[tid] = g_part[tid]; __syncthreads();
    for (int o = 64; o > 0; o >>= 1) { if (tid < o) r[tid] += r[tid + o]; __syncthreads(); }
    float sar = r[0]; __syncthreads();
    r[tid] = g_part[128 + tid]; __syncthreads();
    for (int o = 64; o > 0; o >>= 1) { if (tid < o) r[tid] += r[tid + o]; __syncthreads(); }
    if (tid == 0) {
        out[OFF_AR]  = sar * (0.01f / 16777216.0f);
        out[OFF_TAR] = r[0] * (0.01f / 16711680.0f);
    }
}

// ---------------------------------------------------------------------------
// actor/critic heads
// ---------------------------------------------------------------------------
__global__ __launch_bounds__(256)
void head_kernel(const float* __restrict__ aw, const float* __restrict__ ab,
                 const float* __restrict__ cw, const float* __restrict__ cb,
                 float* __restrict__ out)
{
    __shared__ float ws[19 * 256];
    const int tid = threadIdx.x;
    for (int i = tid; i < Ac * Hc; i += 256) ws[i] = aw[i];
    for (int i = tid; i < Hc; i += 256) ws[Ac * Hc + i] = cw[i];
    __syncthreads();

    const int warp = tid >> 5, lane = tid & 31;
    const size_t m = (size_t)blockIdx.x * 8 + warp;
    const float* h = &out[OFF_HS + m * Hc];

    float p[19];
    #pragma unroll
    for (int o = 0; o < 19; ++o) p[o] = 0.0f;
    #pragma unroll
    for (int kk = 0; kk < 8; ++kk) {
        int k = lane + kk * 32;
        float hv = h[k];
        #pragma unroll
        for (int o = 0; o < 19; ++o) p[o] = fmaf(hv, ws[o * 256 + k], p[o]);
    }
    #pragma unroll
    for (int o = 0; o < 19; ++o)
        #pragma unroll
        for (int off = 16; off > 0; off >>= 1)
            p[o] += __shfl_down_sync(0xffffffffu, p[o], off);

    if (lane == 0) {
        #pragma unroll
        for (int o = 0; o < Ac; ++o)
            out[OFF_LOGITS + m * Ac + o] = p[o] + ab[o];
        out[OFF_VALUES + m] = p[18] + cb[0];
    }
}

// ---------------------------------------------------------------------------
// launcher
// ---------------------------------------------------------------------------
extern "C" void kernel_launch(void* const* d_in, const int* in_sizes, int n_in,
                              void* d_out, int out_size)
{
    const float* obs    = (const float*)d_in[0];
    const float* hxs    = (const float*)d_in[1];
    const float* cxs    = (const float*)d_in[2];
    const float* enc_w1 = (const float*)d_in[3];
    const float* enc_b1 = (const float*)d_in[4];
    const float* enc_w2 = (const float*)d_in[5];
    const float* enc_b2 = (const float*)d_in[6];
    const float* w_ih   = (const float*)d_in[7];
    const float* w_hh   = (const float*)d_in[8];
    const float* b_ih   = (const float*)d_in[9];
    const float* b_hh   = (const float*)d_in[10];
    const float* aw     = (const float*)d_in[11];
    const float* ab     = (const float*)d_in[12];
    const float* cw     = (const float*)d_in[13];
    const float* cb     = (const float*)d_in[14];
    float* out = (float*)d_out;

    void *p_pre, *p_bias;
    void *p_oh, *p_ol, *p_e1h, *p_e1l, *p_e2h, *p_e2l;
    void *p_w1h, *p_w1l, *p_w2h, *p_w2l, *p_wihh, *p_wihl;
    cudaGetSymbolAddress(&p_pre,  g_pre);
    cudaGetSymbolAddress(&p_bias, g_bias);
    cudaGetSymbolAddress(&p_oh,   g_obs_h);  cudaGetSymbolAddress(&p_ol,   g_obs_l);
    cudaGetSymbolAddress(&p_e1h,  g_e1h);    cudaGetSymbolAddress(&p_e1l,  g_e1l);
    cudaGetSymbolAddress(&p_e2h,  g_e2h);    cudaGetSymbolAddress(&p_e2l,  g_e2l);
    cudaGetSymbolAddress(&p_w1h,  g_w1h);    cudaGetSymbolAddress(&p_w1l,  g_w1l);
    cudaGetSymbolAddress(&p_w2h,  g_w2h);    cudaGetSymbolAddress(&p_w2l,  g_w2l);
    cudaGetSymbolAddress(&p_wihh, g_wih_h);  cudaGetSymbolAddress(&p_wihl, g_wih_l);

    cudaFuncSetAttribute(lstm_kernel,
                         cudaFuncAttributeMaxDynamicSharedMemorySize, LSTM_SMEM);

    const int M = Bc * Tc;  // 65536

    // split inputs/weights into bf16 hi/lo planes
    {
        int n;
        n = M * Dc;          conv_split<<<(n + 255) / 256, 256>>>(obs,   (__nv_bfloat16*)p_oh,  (__nv_bfloat16*)p_ol,  n);
        n = Ec * Dc;         conv_split<<<(n + 255) / 256, 256>>>(enc_w1,(__nv_bfloat16*)p_w1h, (__nv_bfloat16*)p_w1l, n);
        n = Ec * Ec;         conv_split<<<(n + 255) / 256, 256>>>(enc_w2,(__nv_bfloat16*)p_w2h, (__nv_bfloat16*)p_w2l, n);
        n = 4 * Hc * Ec;     conv_split<<<(n + 255) / 256, 256>>>(w_ih,  (__nv_bfloat16*)p_wihh,(__nv_bfloat16*)p_wihl,n);
    }
    prep_bias<<<1, 1024>>>(b_ih, b_hh);

    // enc1 = silu(obs @ w1^T + b1) -> bf16 hi/lo planes   (K=128, N=256)
    gemm_mma<<<dim3(M / 128, Ec / 64), 256>>>(
        (const __nv_bfloat16*)p_oh, (const __nv_bfloat16*)p_ol,
        (const __nv_bfloat16*)p_w1h, (const __nv_bfloat16*)p_w1l,
        enc_b1, nullptr, (__nv_bfloat16*)p_e1h, (__nv_bfloat16*)p_e1l, Dc, Ec, 1);
    // enc2 = silu(enc1 @ w2^T + b2) -> bf16 hi/lo planes  (K=256, N=256)
    gemm_mma<<<dim3(M / 128, Ec / 64), 256>>>(
        (const __nv_bfloat16*)p_e1h, (const __nv_bfloat16*)p_e1l,
        (const __nv_bfloat16*)p_w2h, (const __nv_bfloat16*)p_w2l,
        enc_b2, nullptr, (__nv_bfloat16*)p_e2h, (__nv_bfloat16*)p_e2l, Ec, Ec, 1);
    // pre = enc2 @ w_ih^T + (b_ih + b_hh) -> fp32         (K=256, N=1024)
    gemm_mma<<<dim3(M / 128, (4 * Hc) / 64), 256>>>(
        (const __nv_bfloat16*)p_e2h, (const __nv_bfloat16*)p_e2l,
        (const __nv_bfloat16*)p_wihh, (const __nv_bfloat16*)p_wihl,
        (const float*)p_bias, (float*)p_pre, nullptr, nullptr, Ec, 4 * Hc, 0);

    // persistent cluster LSTM
    lstm_kernel<<<128, 128, LSTM_SMEM>>>(hxs, cxs, w_hh, out);
    // losses
    loss_fin<<<1, 128>>>(out);
    // heads
    head_kernel<<<M / 8, 256>>>(aw, ab, cw, cb, out);
}

// round 7
// speedup vs baseline: 1.2176x; 1.0079x over previous
#include <cuda_runtime.h>
#include <cuda_bf16.h>
#include <cstdint>
#include <cstddef>

// ---------------------------------------------------------------------------
// Problem dims
// ---------------------------------------------------------------------------
#define Bc 256
#define Tc 256
#define Dc 128
#define Ec 256
#define Hc 256
#define Ac 18

// Output layout: tuple flattened+concatenated in return order.
static constexpr size_t N_LOGITS = (size_t)Bc * Tc * Ac;
static constexpr size_t NGATE    = (size_t)Bc * Tc * Hc;
static constexpr size_t OFF_LOGITS = 0;
static constexpr size_t OFF_VALUES = OFF_LOGITS + N_LOGITS;
static constexpr size_t OFF_HT     = OFF_VALUES + (size_t)Bc * Tc;
static constexpr size_t OFF_CT     = OFF_HT + (size_t)Bc * Hc;
static constexpr size_t OFF_AR     = OFF_CT + (size_t)Bc * Hc;
static constexpr size_t OFF_TAR    = OFF_AR + 1;
static constexpr size_t OFF_I      = OFF_TAR + 1;
static constexpr size_t OFF_Fg     = OFF_I + NGATE;
static constexpr size_t OFF_Gg     = OFF_Fg + NGATE;
static constexpr size_t OFF_Og     = OFF_Gg + NGATE;
static constexpr size_t OFF_CS     = OFF_Og + NGATE;
static constexpr size_t OFF_HS     = OFF_CS + NGATE;

// ---------------------------------------------------------------------------
// Device scratch (static device globals: allocation-free)
// ---------------------------------------------------------------------------
__device__ float         g_pre [(size_t)Bc * Tc * 4 * Hc];    // 256 MB
__device__ float         g_bias[4 * Hc];
__device__ float         g_part[256];
// split-bf16 planes
__device__ __nv_bfloat16 g_obs_h[(size_t)Bc * Tc * Dc];
__device__ __nv_bfloat16 g_obs_l[(size_t)Bc * Tc * Dc];
__device__ __nv_bfloat16 g_e1h[(size_t)Bc * Tc * Ec];
__device__ __nv_bfloat16 g_e1l[(size_t)Bc * Tc * Ec];
__device__ __nv_bfloat16 g_e2h[(size_t)Bc * Tc * Ec];
__device__ __nv_bfloat16 g_e2l[(size_t)Bc * Tc * Ec];
__device__ __nv_bfloat16 g_w1h[Ec * Dc],      g_w1l[Ec * Dc];
__device__ __nv_bfloat16 g_w2h[Ec * Ec],      g_w2l[Ec * Ec];
__device__ __nv_bfloat16 g_wih_h[4 * Hc * Ec], g_wih_l[4 * Hc * Ec];

// single dynamic-shared declaration for the whole TU
extern __shared__ __align__(1024) char dynsmem[];

// ---------------------------------------------------------------------------
// Math helpers
// ---------------------------------------------------------------------------
__device__ __forceinline__ float sigm(float x) {
    return __fdividef(1.0f, 1.0f + __expf(-x));
}
__device__ __forceinline__ float tanh_f(float x) {
    return 1.0f - __fdividef(2.0f, __expf(2.0f * x) + 1.0f);
}
__device__ __forceinline__ float silu(float x) { return x * sigm(x); }

__device__ __forceinline__ uint32_t smem_u32(const void* p) {
    uint32_t a;
    asm("{ .reg .u64 t; cvta.to.shared.u64 t, %1; cvt.u32.u64 %0, t; }" : "=r"(a) : "l"(p));
    return a;
}

// ---------------------------------------------------------------------------
// warp-MMA + cp.async primitives (baseline PTX, valid at target sm_100)
// ---------------------------------------------------------------------------
__device__ __forceinline__ void ldsm4(uint32_t* r, uint32_t addr) {
    asm volatile("ldmatrix.sync.aligned.m8n8.x4.shared.b16 {%0,%1,%2,%3}, [%4];"
                 : "=r"(r[0]), "=r"(r[1]), "=r"(r[2]), "=r"(r[3]) : "r"(addr));
}
__device__ __forceinline__ void ldsm2(uint32_t* r, uint32_t addr) {
    asm volatile("ldmatrix.sync.aligned.m8n8.x2.shared.b16 {%0,%1}, [%2];"
                 : "=r"(r[0]), "=r"(r[1]) : "r"(addr));
}
__device__ __forceinline__ void mma16816(float* d, const uint32_t* a, const uint32_t* b) {
    asm volatile("mma.sync.aligned.m16n8k16.row.col.f32.bf16.bf16.f32 "
                 "{%0,%1,%2,%3}, {%4,%5,%6,%7}, {%8,%9}, {%0,%1,%2,%3};"
                 : "+f"(d[0]), "+f"(d[1]), "+f"(d[2]), "+f"(d[3])
                 : "r"(a[0]), "r"(a[1]), "r"(a[2]), "r"(a[3]), "r"(b[0]), "r"(b[1]));
}
__device__ __forceinline__ void cp16(uint32_t dst, const void* src) {
    asm volatile("cp.async.cg.shared.global [%0], [%1], 16;" :: "r"(dst), "l"(src));
}
#define CP_COMMIT() asm volatile("cp.async.commit_group;" ::: "memory")

// ---------------------------------------------------------------------------
// fp32 -> (hi, lo) bf16 split
// ---------------------------------------------------------------------------
__global__ void conv_split(const float* __restrict__ in, __nv_bfloat16* __restrict__ h,
                           __nv_bfloat16* __restrict__ l, int n)
{
    int i = blockIdx.x * blockDim.x + threadIdx.x;
    if (i >= n) return;
    float x = in[i];
    __nv_bfloat16 hb = __float2bfloat16(x);
    h[i] = hb;
    l[i] = __float2bfloat16(x - __bfloat162float(hb));
}

// ---------------------------------------------------------------------------
// split-bf16 tensor-core GEMM: D[m,n] = sum_k A[m,k]*W[n,k]  (fp32 accum)
// 3 passes: Ah*Bh + Al*Bh + Ah*Bl.
// CTA tile 128x128, 8 warps (2m x 4n), warp tile 64x32, BK=32.
// 2-stage cp.async double-buffered pipeline.
// mode 0: outF = D + bias[n];  mode 1: silu(D+bias) -> bf16 hi/lo planes.
// SMEM rows 40 bf16 (80 B) as in the proven R6 layout.
// ---------------------------------------------------------------------------
#define PA_H 0
#define PA_L 10240
#define PB_H 20480
#define PB_L 30720
#define GSTAGE 40960
#define GDATA_OFF 512
#define GEMM_SMEM_TOT (GDATA_OFF + 2 * GSTAGE)   // 82432 bytes

__device__ __forceinline__ void gemm_load_stage(
    uint32_t sbase,
    const __nv_bfloat16* __restrict__ Ah, const __nv_bfloat16* __restrict__ Al,
    const __nv_bfloat16* __restrict__ Wh, const __nv_bfloat16* __restrict__ Wl,
    int m0, int n0, int K, int k0, int tid)
{
    #pragma unroll
    for (int i = 0; i < 2; ++i) {
        int idx = tid + (i << 8);
        int row = idx >> 2, c = idx & 3;
        uint32_t d = (uint32_t)(row * 80 + c * 16);
        size_t ga = (size_t)(m0 + row) * K + k0 + c * 8;
        size_t gb = (size_t)(n0 + row) * K + k0 + c * 8;
        cp16(sbase + PA_H + d, Ah + ga);
        cp16(sbase + PA_L + d, Al + ga);
        cp16(sbase + PB_H + d, Wh + gb);
        cp16(sbase + PB_L + d, Wl + gb);
    }
}

__global__ __launch_bounds__(256)
void gemm_mma(const __nv_bfloat16* __restrict__ Ah, const __nv_bfloat16* __restrict__ Al,
              const __nv_bfloat16* __restrict__ Wh, const __nv_bfloat16* __restrict__ Wl,
              const float* __restrict__ bias, float* __restrict__ outF,
              __nv_bfloat16* __restrict__ outH, __nv_bfloat16* __restrict__ outL,
              int K, int N, int mode)
{
    const uint32_t sb = smem_u32(dynsmem);
    float* sbias = (float*)dynsmem;

    const int tid  = threadIdx.x;
    const int lane = tid & 31;
    const int w    = tid >> 5;
    const int wm   = w >> 2;         // 0..1 -> rows wm*64
    const int wn   = w & 3;          // 0..3 -> cols wn*32
    const int m0   = blockIdx.x * 128;
    const int n0   = blockIdx.y * 128;

    if (tid < 128) sbias[tid] = bias[n0 + tid];

    // lane-dependent ldmatrix source offsets (proven R6 fragment math)
    const int aro  = (lane & 7) + ((lane >> 3) & 1) * 8;
    const int ac16 = (lane >> 4) & 1;
    const int bl8  = lane & 15;
    const int bro  = bl8 & 7;
    const int bc16 = (bl8 >> 3) & 1;

    const uint32_t aBase = (uint32_t)aro * 80 + ac16 * 16;  // + (wm*64+mt*16)*80 + ks*32
    const uint32_t bBase = (uint32_t)bro * 80 + bc16 * 16;  // + (wn*32+nt*8)*80 + ks*32

    float acc[4][4][4];
    #pragma unroll
    for (int mt = 0; mt < 4; ++mt)
        #pragma unroll
        for (int nt = 0; nt < 4; ++nt)
            #pragma unroll
            for (int r = 0; r < 4; ++r) acc[mt][nt][r] = 0.0f;

    const int NCH = K >> 5;
    gemm_load_stage(sb + GDATA_OFF, Ah, Al, Wh, Wl, m0, n0, K, 0, tid);
    CP_COMMIT();

    for (int ch = 0; ch < NCH; ++ch) {
        if (ch + 1 < NCH) {
            gemm_load_stage(sb + GDATA_OFF + ((ch + 1) & 1) * GSTAGE,
                            Ah, Al, Wh, Wl, m0, n0, K, (ch + 1) << 5, tid);
            CP_COMMIT();
            asm volatile("cp.async.wait_group 1;" ::: "memory");
        } else {
            asm volatile("cp.async.wait_group 0;" ::: "memory");
        }
        __syncthreads();

        const uint32_t st = sb + GDATA_OFF + (ch & 1) * GSTAGE;
        #pragma unroll
        for (int ks = 0; ks < 2; ++ks) {
            uint32_t bh[4][2], bl[4][2];
            #pragma unroll
            for (int nt = 0; nt < 4; ++nt) {
                uint32_t o = bBase + (uint32_t)(wn * 32 + nt * 8) * 80 + ks * 32;
                ldsm2(bh[nt], st + PB_H + o);
                ldsm2(bl[nt], st + PB_L + o);
            }
            #pragma unroll
            for (int mt = 0; mt < 4; ++mt) {
                uint32_t ah[4], al[4];
                uint32_t o = aBase + (uint32_t)(wm * 64 + mt * 16) * 80 + ks * 32;
                ldsm4(ah, st + PA_H + o);
                ldsm4(al, st + PA_L + o);
                #pragma unroll
                for (int nt = 0; nt < 4; ++nt) {
                    mma16816(acc[mt][nt], ah, bh[nt]);
                    mma16816(acc[mt][nt], al, bh[nt]);
                    mma16816(acc[mt][nt], ah, bl[nt]);
                }
            }
        }
        __syncthreads();
    }

    // epilogue
    #pragma unroll
    for (int mt = 0; mt < 4; ++mt) {
        const int r0 = m0 + wm * 64 + mt * 16 + (lane >> 2);
        #pragma unroll
        for (int nt = 0; nt < 4; ++nt) {
            const int cl = wn * 32 + nt * 8 + (lane & 3) * 2;
            const int c  = n0 + cl;
            float v0 = acc[mt][nt][0] + sbias[cl];
            float v1 = acc[mt][nt][1] + sbias[cl + 1];
            float v2 = acc[mt][nt][2] + sbias[cl];
            float v3 = acc[mt][nt][3] + sbias[cl + 1];
            if (mode == 0) {
                *(float2*)&outF[(size_t)r0 * N + c]       = make_float2(v0, v1);
                *(float2*)&outF[(size_t)(r0 + 8) * N + c] = make_float2(v2, v3);
            } else {
                v0 = silu(v0); v1 = silu(v1); v2 = silu(v2); v3 = silu(v3);
                __nv_bfloat16 h0 = __float2bfloat16(v0), h1 = __float2bfloat16(v1);
                __nv_bfloat16 h2 = __float2bfloat16(v2), h3 = __float2bfloat16(v3);
                __nv_bfloat16 l0 = __float2bfloat16(v0 - __bfloat162float(h0));
                __nv_bfloat16 l1 = __float2bfloat16(v1 - __bfloat162float(h1));
                __nv_bfloat16 l2 = __float2bfloat16(v2 - __bfloat162float(h2));
                __nv_bfloat16 l3 = __float2bfloat16(v3 - __bfloat162float(h3));
                size_t o0 = (size_t)r0 * N + c, o1 = (size_t)(r0 + 8) * N + c;
                *(__nv_bfloat162*)&outH[o0] = __nv_bfloat162(h0, h1);
                *(__nv_bfloat162*)&outL[o0] = __nv_bfloat162(l0, l1);
                *(__nv_bfloat162*)&outH[o1] = __nv_bfloat162(h2, h3);
                *(__nv_bfloat162*)&outL[o1] = __nv_bfloat162(l2, l3);
            }
        }
    }
}

// ---------------------------------------------------------------------------
// bias prep: g_bias = b_ih + b_hh
// ---------------------------------------------------------------------------
__global__ void prep_bias(const float* __restrict__ bih, const float* __restrict__ bhh)
{
    int i = threadIdx.x;
    g_bias[i] = bih[i] + bhh[i];
}

// ---------------------------------------------------------------------------
// Persistent cluster LSTM (proven in R2/R6)
// ---------------------------------------------------------------------------
__device__ __forceinline__ void push_h8(unsigned laddr, float v)
{
    #pragma unroll
    for (int rk = 0; rk < 8; ++rk) {
        unsigned ra;
        asm volatile("mapa.shared::cluster.u32 %0, %1, %2;" : "=r"(ra) : "r"(laddr), "r"(rk));
        asm volatile("st.shared::cluster.f32 [%0], %1;" :: "r"(ra), "f"(v));
    }
}
__device__ __forceinline__ void cluster_sync_()
{
    asm volatile("barrier.cluster.arrive.aligned;" ::: "memory");
    asm volatile("barrier.cluster.wait.aligned;"   ::: "memory");
}

#define WSH_STRIDE 260
#define LSTM_SMEM (128 * WSH_STRIDE * 4 + 2 * 16 * 256 * 4)

__global__ void __cluster_dims__(8, 1, 1) __launch_bounds__(128, 1)
lstm_kernel(const float* __restrict__ hxs, const float* __restrict__ cxs,
            const float* __restrict__ w_hh, float* __restrict__ out)
{
    float* smem = (float*)dynsmem;
    float* wsh = smem;
    float* hb0 = smem + 128 * WSH_STRIDE;
    float* hb1 = hb0 + 16 * 256;

    const int tid  = threadIdx.x;
    const int grp  = blockIdx.x >> 3;
    const int rank = blockIdx.x & 7;
    const int b0   = grp * 16;
    const int u0   = rank * 32;
    const int j    = tid & 31;
    const int s    = tid >> 5;

    for (int idx = tid; idx < 128 * 64; idx += 128) {
        int rr = idx >> 6;
        int k4 = idx & 63;
        int q = rr >> 5, jj = rr & 31;
        float4 v = *(const float4*)&w_hh[(size_t)((q << 8) + u0 + jj) * Hc + (k4 << 2)];
        *(float4*)&wsh[rr * WSH_STRIDE + (k4 << 2)] = v;
    }
    for (int idx = tid; idx < 16 * 64; idx += 128) {
        int row = idx >> 6, k4 = idx & 63;
        *(float4*)&hb0[row * 256 + (k4 << 2)] =
            *(const float4*)&hxs[(size_t)(b0 + row) * Hc + (k4 << 2)];
    }

    int   gr[4]; int ro[4];
    float c[4], hp[4];
    #pragma unroll
    for (int i = 0; i < 4; ++i) {
        int row = s + 4 * i;
        gr[i] = b0 + row;
        ro[i] = row * 256;
        c[i]  = cxs[(size_t)gr[i] * Hc + u0 + j];
        hp[i] = 0.0f;
    }
    float ar = 0.0f, tar = 0.0f;
    __syncthreads();

    const float* w0 = &wsh[(0 * 32 + j) * WSH_STRIDE];
    const float* w1 = &wsh[(1 * 32 + j) * WSH_STRIDE];
    const float* w2 = &wsh[(2 * 32 + j) * WSH_STRIDE];
    const float* w3 = &wsh[(3 * 32 + j) * WSH_STRIDE];

    int cur = 0;
    for (int t = 0; t < Tc; ++t) {
        const float* hc = cur ? hb1 : hb0;
        float*       hn = cur ? hb0 : hb1;

        float acc[4][4];
        #pragma unroll
        for (int i = 0; i < 4; ++i) {
            const float* pr = &g_pre[(size_t)(gr[i] * Tc + t) * (4 * Hc) + u0 + j];
            acc[i][0] = pr[0];   acc[i][1] = pr[256];
            acc[i][2] = pr[512]; acc[i][3] = pr[768];
        }

        #pragma unroll 4
        for (int k4 = 0; k4 < 64; ++k4) {
            const int k = k4 << 2;
            float4 a = *(const float4*)&w0[k];
            float4 b = *(const float4*)&w1[k];
            float4 g = *(const float4*)&w2[k];
            float4 o = *(const float4*)&w3[k];
            #pragma unroll
            for (int i = 0; i < 4; ++i) {
                float4 h4 = *(const float4*)&hc[ro[i] + k];
                acc[i][0] = fmaf(h4.x, a.x, acc[i][0]);
                acc[i][0] = fmaf(h4.y, a.y, acc[i][0]);
                acc[i][0] = fmaf(h4.z, a.z, acc[i][0]);
                acc[i][0] = fmaf(h4.w, a.w, acc[i][0]);
                acc[i][1] = fmaf(h4.x, b.x, acc[i][1]);
                acc[i][1] = fmaf(h4.y, b.y, acc[i][1]);
                acc[i][1] = fmaf(h4.z, b.z, acc[i][1]);
                acc[i][1] = fmaf(h4.w, b.w, acc[i][1]);
                acc[i][2] = fmaf(h4.x, g.x, acc[i][2]);
                acc[i][2] = fmaf(h4.y, g.y, acc[i][2]);
                acc[i][2] = fmaf(h4.z, g.z, acc[i][2]);
                acc[i][2] = fmaf(h4.w, g.w, acc[i][2]);
                acc[i][3] = fmaf(h4.x, o.x, acc[i][3]);
                acc[i][3] = fmaf(h4.y, o.y, acc[i][3]);
                acc[i][3] = fmaf(h4.z, o.z, acc[i][3]);
                acc[i][3] = fmaf(h4.w, o.w, acc[i][3]);
            }
        }

        #pragma unroll
        for (int i = 0; i < 4; ++i) {
            float iv = sigm(acc[i][0]);
            float fv = sigm(acc[i][1]);
            float gv = tanh_f(acc[i][2]);
            float ov = sigm(acc[i][3]);
            float c2 = fmaf(fv, c[i], iv * gv);
            float h2 = ov * tanh_f(c2);
            c[i] = c2;
            ar = fmaf(h2, h2, ar);
            float d = h2 - hp[i];
            if (t > 0) tar = fmaf(d, d, tar);
            hp[i] = h2;

            const size_t base = (size_t)(gr[i] * Tc + t) * Hc + u0 + j;
            __stcs(&out[OFF_I  + base], iv);
            __stcs(&out[OFF_Fg + base], fv);
            __stcs(&out[OFF_Gg + base], gv);
            __stcs(&out[OFF_Og + base], ov);
            __stcs(&out[OFF_CS + base], c2);
            __stcs(&out[OFF_HS + base], h2);
            if (t == Tc - 1) {
                out[OFF_HT + (size_t)gr[i] * Hc + u0 + j] = h2;
                out[OFF_CT + (size_t)gr[i] * Hc + u0 + j] = c2;
            }
            unsigned laddr = (unsigned)__cvta_generic_to_shared(&hn[ro[i] + u0 + j]);
            push_h8(laddr, h2);
        }

        cluster_sync_();
        cur ^= 1;
    }

    __shared__ float red[128];
    red[tid] = ar; __syncthreads();
    for (int o = 64; o > 0; o >>= 1) { if (tid < o) red[tid] += red[tid + o]; __syncthreads(); }
    if (tid == 0) g_part[blockIdx.x] = red[0];
    __syncthreads();
    red[tid] = tar; __syncthreads();
    for (int o = 64; o > 0; o >>= 1) { if (tid < o) red[tid] += red[tid + o]; __syncthreads(); }
    if (tid == 0) g_part[128 + blockIdx.x] = red[0];
}

// ---------------------------------------------------------------------------
// loss finalize
// ---------------------------------------------------------------------------
__global__ void loss_fin(float* __restrict__ out)
{
    __shared__ float r[128];
    int tid = threadIdx.x;
    r[tid] = g_part[tid]; __syncthreads();
    for (int o = 64; o > 0; o >>= 1) { if (tid < o) r[tid] += r[tid + o]; __syncthreads(); }
    float sar = r[0]; __syncthreads();
    r[tid] = g_part[128 + tid]; __syncthreads();
    for (int o = 64; o > 0; o >>= 1) { if (tid < o) r[tid] += r[tid + o]; __syncthreads(); }
    if (tid == 0) {
        out[OFF_AR]  = sar * (0.01f / 16777216.0f);
        out[OFF_TAR] = r[0] * (0.01f / 16711680.0f);
    }
}

// ---------------------------------------------------------------------------
// actor/critic heads
// ---------------------------------------------------------------------------
__global__ __launch_bounds__(256)
void head_kernel(const float* __restrict__ aw, const float* __restrict__ ab,
                 const float* __restrict__ cw, const float* __restrict__ cb,
                 float* __restrict__ out)
{
    __shared__ float ws[19 * 256];
    const int tid = threadIdx.x;
    for (int i = tid; i < Ac * Hc; i += 256) ws[i] = aw[i];
    for (int i = tid; i < Hc; i += 256) ws[Ac * Hc + i] = cw[i];
    __syncthreads();

    const int warp = tid >> 5, lane = tid & 31;
    const size_t m = (size_t)blockIdx.x * 8 + warp;
    const float* h = &out[OFF_HS + m * Hc];

    float p[19];
    #pragma unroll
    for (int o = 0; o < 19; ++o) p[o] = 0.0f;
    #pragma unroll
    for (int kk = 0; kk < 8; ++kk) {
        int k = lane + kk * 32;
        float hv = h[k];
        #pragma unroll
        for (int o = 0; o < 19; ++o) p[o] = fmaf(hv, ws[o * 256 + k], p[o]);
    }
    #pragma unroll
    for (int o = 0; o < 19; ++o)
        #pragma unroll
        for (int off = 16; off > 0; off >>= 1)
            p[o] += __shfl_down_sync(0xffffffffu, p[o], off);

    if (lane == 0) {
        #pragma unroll
        for (int o = 0; o < Ac; ++o)
            out[OFF_LOGITS + m * Ac + o] = p[o] + ab[o];
        out[OFF_VALUES + m] = p[18] + cb[0];
    }
}

// ---------------------------------------------------------------------------
// launcher
// ---------------------------------------------------------------------------
extern "C" void kernel_launch(void* const* d_in, const int* in_sizes, int n_in,
                              void* d_out, int out_size)
{
    const float* obs    = (const float*)d_in[0];
    const float* hxs    = (const float*)d_in[1];
    const float* cxs    = (const float*)d_in[2];
    const float* enc_w1 = (const float*)d_in[3];
    const float* enc_b1 = (const float*)d_in[4];
    const float* enc_w2 = (const float*)d_in[5];
    const float* enc_b2 = (const float*)d_in[6];
    const float* w_ih   = (const float*)d_in[7];
    const float* w_hh   = (const float*)d_in[8];
    const float* b_ih   = (const float*)d_in[9];
    const float* b_hh   = (const float*)d_in[10];
    const float* aw     = (const float*)d_in[11];
    const float* ab     = (const float*)d_in[12];
    const float* cw     = (const float*)d_in[13];
    const float* cb     = (const float*)d_in[14];
    float* out = (float*)d_out;

    void *p_pre, *p_bias;
    void *p_oh, *p_ol, *p_e1h, *p_e1l, *p_e2h, *p_e2l;
    void *p_w1h, *p_w1l, *p_w2h, *p_w2l, *p_wihh, *p_wihl;
    cudaGetSymbolAddress(&p_pre,  g_pre);
    cudaGetSymbolAddress(&p_bias, g_bias);
    cudaGetSymbolAddress(&p_oh,   g_obs_h);  cudaGetSymbolAddress(&p_ol,   g_obs_l);
    cudaGetSymbolAddress(&p_e1h,  g_e1h);    cudaGetSymbolAddress(&p_e1l,  g_e1l);
    cudaGetSymbolAddress(&p_e2h,  g_e2h);    cudaGetSymbolAddress(&p_e2l,  g_e2l);
    cudaGetSymbolAddress(&p_w1h,  g_w1h);    cudaGetSymbolAddress(&p_w1l,  g_w1l);
    cudaGetSymbolAddress(&p_w2h,  g_w2h);    cudaGetSymbolAddress(&p_w2l,  g_w2l);
    cudaGetSymbolAddress(&p_wihh, g_wih_h);  cudaGetSymbolAddress(&p_wihl, g_wih_l);

    cudaFuncSetAttribute(lstm_kernel,
                         cudaFuncAttributeMaxDynamicSharedMemorySize, LSTM_SMEM);
    cudaFuncSetAttribute(gemm_mma,
                         cudaFuncAttributeMaxDynamicSharedMemorySize, GEMM_SMEM_TOT);

    const int M = Bc * Tc;  // 65536

    // split inputs/weights into bf16 hi/lo planes
    {
        int n;
        n = M * Dc;          conv_split<<<(n + 255) / 256, 256>>>(obs,   (__nv_bfloat16*)p_oh,  (__nv_bfloat16*)p_ol,  n);
        n = Ec * Dc;         conv_split<<<(n + 255) / 256, 256>>>(enc_w1,(__nv_bfloat16*)p_w1h, (__nv_bfloat16*)p_w1l, n);
        n = Ec * Ec;         conv_split<<<(n + 255) / 256, 256>>>(enc_w2,(__nv_bfloat16*)p_w2h, (__nv_bfloat16*)p_w2l, n);
        n = 4 * Hc * Ec;     conv_split<<<(n + 255) / 256, 256>>>(w_ih,  (__nv_bfloat16*)p_wihh,(__nv_bfloat16*)p_wihl,n);
    }
    prep_bias<<<1, 1024>>>(b_ih, b_hh);

    // enc1 = silu(obs @ w1^T + b1) -> bf16 hi/lo planes   (K=128, N=256)
    gemm_mma<<<dim3(M / 128, Ec / 128), 256, GEMM_SMEM_TOT>>>(
        (const __nv_bfloat16*)p_oh, (const __nv_bfloat16*)p_ol,
        (const __nv_bfloat16*)p_w1h, (const __nv_bfloat16*)p_w1l,
        enc_b1, nullptr, (__nv_bfloat16*)p_e1h, (__nv_bfloat16*)p_e1l, Dc, Ec, 1);
    // enc2 = silu(enc1 @ w2^T + b2) -> bf16 hi/lo planes  (K=256, N=256)
    gemm_mma<<<dim3(M / 128, Ec / 128), 256, GEMM_SMEM_TOT>>>(
        (const __nv_bfloat16*)p_e1h, (const __nv_bfloat16*)p_e1l,
        (const __nv_bfloat16*)p_w2h, (const __nv_bfloat16*)p_w2l,
        enc_b2, nullptr, (__nv_bfloat16*)p_e2h, (__nv_bfloat16*)p_e2l, Ec, Ec, 1);
    // pre = enc2 @ w_ih^T + (b_ih + b_hh) -> fp32         (K=256, N=1024)
    gemm_mma<<<dim3(M / 128, (4 * Hc) / 128), 256, GEMM_SMEM_TOT>>>(
        (const __nv_bfloat16*)p_e2h, (const __nv_bfloat16*)p_e2l,
        (const __nv_bfloat16*)p_wihh, (const __nv_bfloat16*)p_wihl,
        (const float*)p_bias, (float*)p_pre, nullptr, nullptr, Ec, 4 * Hc, 0);

    // persistent cluster LSTM
    lstm_kernel<<<128, 128, LSTM_SMEM>>>(hxs, cxs, w_hh, out);
    // losses
    loss_fin<<<1, 128>>>(out);
    // heads
    head_kernel<<<M / 8, 256>>>(aw, ab, cw, cb, out);
}

// round 8
// speedup vs baseline: 1.3433x; 1.1032x over previous
#include <cuda_runtime.h>
#include <cuda_fp16.h>
#include <cstdint>
#include <cstddef>

// ---------------------------------------------------------------------------
// Problem dims
// ---------------------------------------------------------------------------
#define Bc 256
#define Tc 256
#define Dc 128
#define Ec 256
#define Hc 256
#define Ac 18

// Output layout: tuple flattened+concatenated in return order.
static constexpr size_t N_LOGITS = (size_t)Bc * Tc * Ac;
static constexpr size_t NGATE    = (size_t)Bc * Tc * Hc;
static constexpr size_t OFF_LOGITS = 0;
static constexpr size_t OFF_VALUES = OFF_LOGITS + N_LOGITS;
static constexpr size_t OFF_HT     = OFF_VALUES + (size_t)Bc * Tc;
static constexpr size_t OFF_CT     = OFF_HT + (size_t)Bc * Hc;
static constexpr size_t OFF_AR     = OFF_CT + (size_t)Bc * Hc;
static constexpr size_t OFF_TAR    = OFF_AR + 1;
static constexpr size_t OFF_I      = OFF_TAR + 1;
static constexpr size_t OFF_Fg     = OFF_I + NGATE;
static constexpr size_t OFF_Gg     = OFF_Fg + NGATE;
static constexpr size_t OFF_Og     = OFF_Gg + NGATE;
static constexpr size_t OFF_CS     = OFF_Og + NGATE;
static constexpr size_t OFF_HS     = OFF_CS + NGATE;

// ---------------------------------------------------------------------------
// Device scratch (static device globals: allocation-free)
// ---------------------------------------------------------------------------
__device__ float  g_pre [(size_t)Bc * Tc * 4 * Hc];    // 256 MB
__device__ float  g_bias[4 * Hc];
__device__ float  g_part[256];
// fp16 planes: activations hi+lo, weights hi only
__device__ __half g_obs_h[(size_t)Bc * Tc * Dc];
__device__ __half g_obs_l[(size_t)Bc * Tc * Dc];
__device__ __half g_e1h[(size_t)Bc * Tc * Ec];
__device__ __half g_e1l[(size_t)Bc * Tc * Ec];
__device__ __half g_e2h[(size_t)Bc * Tc * Ec];
__device__ __half g_e2l[(size_t)Bc * Tc * Ec];
__device__ __half g_w1h[Ec * Dc];
__device__ __half g_w2h[Ec * Ec];
__device__ __half g_wih_h[4 * Hc * Ec];

// single dynamic-shared declaration for the whole TU
extern __shared__ __align__(1024) char dynsmem[];

// ---------------------------------------------------------------------------
// Math helpers
// ---------------------------------------------------------------------------
__device__ __forceinline__ float sigm(float x) {
    return __fdividef(1.0f, 1.0f + __expf(-x));
}
__device__ __forceinline__ float tanh_f(float x) {
    return 1.0f - __fdividef(2.0f, __expf(2.0f * x) + 1.0f);
}
__device__ __forceinline__ float silu(float x) { return x * sigm(x); }

__device__ __forceinline__ uint32_t smem_u32(const void* p) {
    uint32_t a;
    asm("{ .reg .u64 t; cvta.to.shared.u64 t, %1; cvt.u32.u64 %0, t; }" : "=r"(a) : "l"(p));
    return a;
}

// ---------------------------------------------------------------------------
// warp-MMA + cp.async primitives (baseline PTX, valid at target sm_100)
// ---------------------------------------------------------------------------
__device__ __forceinline__ void ldsm4(uint32_t* r, uint32_t addr) {
    asm volatile("ldmatrix.sync.aligned.m8n8.x4.shared.b16 {%0,%1,%2,%3}, [%4];"
                 : "=r"(r[0]), "=r"(r[1]), "=r"(r[2]), "=r"(r[3]) : "r"(addr));
}
__device__ __forceinline__ void ldsm2(uint32_t* r, uint32_t addr) {
    asm volatile("ldmatrix.sync.aligned.m8n8.x2.shared.b16 {%0,%1}, [%2];"
                 : "=r"(r[0]), "=r"(r[1]) : "r"(addr));
}
__device__ __forceinline__ void mma16816h(float* d, const uint32_t* a, const uint32_t* b) {
    asm volatile("mma.sync.aligned.m16n8k16.row.col.f32.f16.f16.f32 "
                 "{%0,%1,%2,%3}, {%4,%5,%6,%7}, {%8,%9}, {%0,%1,%2,%3};"
                 : "+f"(d[0]), "+f"(d[1]), "+f"(d[2]), "+f"(d[3])
                 : "r"(a[0]), "r"(a[1]), "r"(a[2]), "r"(a[3]), "r"(b[0]), "r"(b[1]));
}
__device__ __forceinline__ void cp16(uint32_t dst, const void* src) {
    asm volatile("cp.async.cg.shared.global [%0], [%1], 16;" :: "r"(dst), "l"(src));
}
#define CP_COMMIT() asm volatile("cp.async.commit_group;" ::: "memory")

// ---------------------------------------------------------------------------
// fp32 -> fp16 conversions
// ---------------------------------------------------------------------------
__global__ void conv_split_h(const float* __restrict__ in, __half* __restrict__ h,
                             __half* __restrict__ l, int n)
{
    int i = blockIdx.x * blockDim.x + threadIdx.x;
    if (i >= n) return;
    float x = in[i];
    __half hb = __float2half_rn(x);
    h[i] = hb;
    l[i] = __float2half_rn(x - __half2float(hb));
}
__global__ void conv_h(const float* __restrict__ in, __half* __restrict__ h, int n)
{
    int i = blockIdx.x * blockDim.x + threadIdx.x;
    if (i >= n) return;
    h[i] = __float2half_rn(in[i]);
}

// ---------------------------------------------------------------------------
// split-fp16 tensor-core GEMM: D[m,n] = sum_k A[m,k]*W[n,k]  (fp32 accum)
// 2 passes: Ah*Wh + Al*Wh  (A split hi/lo, W hi-only).
// CTA tile 128x128, 8 warps (2m x 4n), warp tile 64x32, BK=32.
// 2-stage cp.async double-buffered pipeline. SMEM rows 40 halves (80 B).
// mode 0: outF = D + bias[n];  mode 1: silu(D+bias) -> fp16 hi/lo planes.
// ---------------------------------------------------------------------------
#define PA_H 0
#define PA_L 10240
#define PB_H 20480
#define GSTAGE 30720
#define GDATA_OFF 512
#define GEMM_SMEM_TOT (GDATA_OFF + 2 * GSTAGE)   // 61952 bytes

__device__ __forceinline__ void gemm_load_stage(
    uint32_t sbase,
    const __half* __restrict__ Ah, const __half* __restrict__ Al,
    const __half* __restrict__ Wh,
    int m0, int n0, int K, int k0, int tid)
{
    #pragma unroll
    for (int i = 0; i < 2; ++i) {
        int idx = tid + (i << 8);
        int row = idx >> 2, c = idx & 3;
        uint32_t d = (uint32_t)(row * 80 + c * 16);
        size_t ga = (size_t)(m0 + row) * K + k0 + c * 8;
        size_t gb = (size_t)(n0 + row) * K + k0 + c * 8;
        cp16(sbase + PA_H + d, Ah + ga);
        cp16(sbase + PA_L + d, Al + ga);
        cp16(sbase + PB_H + d, Wh + gb);
    }
}

__global__ __launch_bounds__(256)
void gemm_mma(const __half* __restrict__ Ah, const __half* __restrict__ Al,
              const __half* __restrict__ Wh,
              const float* __restrict__ bias, float* __restrict__ outF,
              __half* __restrict__ outH, __half* __restrict__ outL,
              int K, int N, int mode)
{
    const uint32_t sb = smem_u32(dynsmem);
    float* sbias = (float*)dynsmem;

    const int tid  = threadIdx.x;
    const int lane = tid & 31;
    const int w    = tid >> 5;
    const int wm   = w >> 2;         // 0..1 -> rows wm*64
    const int wn   = w & 3;          // 0..3 -> cols wn*32
    const int m0   = blockIdx.x * 128;
    const int n0   = blockIdx.y * 128;

    if (tid < 128) sbias[tid] = bias[n0 + tid];

    const int aro  = (lane & 7) + ((lane >> 3) & 1) * 8;
    const int ac16 = (lane >> 4) & 1;
    const int bl8  = lane & 15;
    const int bro  = bl8 & 7;
    const int bc16 = (bl8 >> 3) & 1;

    const uint32_t aBase = (uint32_t)aro * 80 + ac16 * 16;
    const uint32_t bBase = (uint32_t)bro * 80 + bc16 * 16;

    float acc[4][4][4];
    #pragma unroll
    for (int mt = 0; mt < 4; ++mt)
        #pragma unroll
        for (int nt = 0; nt < 4; ++nt)
            #pragma unroll
            for (int r = 0; r < 4; ++r) acc[mt][nt][r] = 0.0f;

    const int NCH = K >> 5;
    gemm_load_stage(sb + GDATA_OFF, Ah, Al, Wh, m0, n0, K, 0, tid);
    CP_COMMIT();

    for (int ch = 0; ch < NCH; ++ch) {
        if (ch + 1 < NCH) {
            gemm_load_stage(sb + GDATA_OFF + ((ch + 1) & 1) * GSTAGE,
                            Ah, Al, Wh, m0, n0, K, (ch + 1) << 5, tid);
            CP_COMMIT();
            asm volatile("cp.async.wait_group 1;" ::: "memory");
        } else {
            asm volatile("cp.async.wait_group 0;" ::: "memory");
        }
        __syncthreads();

        const uint32_t st = sb + GDATA_OFF + (ch & 1) * GSTAGE;
        #pragma unroll
        for (int ks = 0; ks < 2; ++ks) {
            uint32_t bh[4][2];
            #pragma unroll
            for (int nt = 0; nt < 4; ++nt) {
                uint32_t o = bBase + (uint32_t)(wn * 32 + nt * 8) * 80 + ks * 32;
                ldsm2(bh[nt], st + PB_H + o);
            }
            #pragma unroll
            for (int mt = 0; mt < 4; ++mt) {
                uint32_t ah[4], al[4];
                uint32_t o = aBase + (uint32_t)(wm * 64 + mt * 16) * 80 + ks * 32;
                ldsm4(ah, st + PA_H + o);
                ldsm4(al, st + PA_L + o);
                #pragma unroll
                for (int nt = 0; nt < 4; ++nt) {
                    mma16816h(acc[mt][nt], ah, bh[nt]);
                    mma16816h(acc[mt][nt], al, bh[nt]);
                }
            }
        }
        __syncthreads();
    }

    // epilogue
    #pragma unroll
    for (int mt = 0; mt < 4; ++mt) {
        const int r0 = m0 + wm * 64 + mt * 16 + (lane >> 2);
        #pragma unroll
        for (int nt = 0; nt < 4; ++nt) {
            const int cl = wn * 32 + nt * 8 + (lane & 3) * 2;
            const int c  = n0 + cl;
            float v0 = acc[mt][nt][0] + sbias[cl];
            float v1 = acc[mt][nt][1] + sbias[cl + 1];
            float v2 = acc[mt][nt][2] + sbias[cl];
            float v3 = acc[mt][nt][3] + sbias[cl + 1];
            if (mode == 0) {
                *(float2*)&outF[(size_t)r0 * N + c]       = make_float2(v0, v1);
                *(float2*)&outF[(size_t)(r0 + 8) * N + c] = make_float2(v2, v3);
            } else {
                v0 = silu(v0); v1 = silu(v1); v2 = silu(v2); v3 = silu(v3);
                __half h0 = __float2half_rn(v0), h1 = __float2half_rn(v1);
                __half h2 = __float2half_rn(v2), h3 = __float2half_rn(v3);
                __half l0 = __float2half_rn(v0 - __half2float(h0));
                __half l1 = __float2half_rn(v1 - __half2float(h1));
                __half l2 = __float2half_rn(v2 - __half2float(h2));
                __half l3 = __float2half_rn(v3 - __half2float(h3));
                size_t o0 = (size_t)r0 * N + c, o1 = (size_t)(r0 + 8) * N + c;
                *(__half2*)&outH[o0] = __halves2half2(h0, h1);
                *(__half2*)&outL[o0] = __halves2half2(l0, l1);
                *(__half2*)&outH[o1] = __halves2half2(h2, h3);
                *(__half2*)&outL[o1] = __halves2half2(l2, l3);
            }
        }
    }
}

// ---------------------------------------------------------------------------
// bias prep: g_bias = b_ih + b_hh
// ---------------------------------------------------------------------------
__global__ void prep_bias(const float* __restrict__ bih, const float* __restrict__ bhh)
{
    int i = threadIdx.x;
    g_bias[i] = bih[i] + bhh[i];
}

// ---------------------------------------------------------------------------
// Persistent cluster LSTM. R2-proven structure + two new micro-opts:
//   (1) g_pre prefetched one step ahead into registers
//   (2) mapa hoisted out of the per-step push loop
// ---------------------------------------------------------------------------
__device__ __forceinline__ void cluster_sync_()
{
    asm volatile("barrier.cluster.arrive.aligned;" ::: "memory");
    asm volatile("barrier.cluster.wait.aligned;"   ::: "memory");
}

#define WSH_STRIDE 260
#define LSTM_SMEM (128 * WSH_STRIDE * 4 + 2 * 16 * 256 * 4)

__global__ void __cluster_dims__(8, 1, 1) __launch_bounds__(128, 1)
lstm_kernel(const float* __restrict__ hxs, const float* __restrict__ cxs,
            const float* __restrict__ w_hh, float* __restrict__ out)
{
    float* smem = (float*)dynsmem;
    float* wsh = smem;
    float* hb0 = smem + 128 * WSH_STRIDE;
    float* hb1 = hb0 + 16 * 256;

    const int tid  = threadIdx.x;
    const int grp  = blockIdx.x >> 3;
    const int rank = blockIdx.x & 7;
    const int b0   = grp * 16;
    const int u0   = rank * 32;
    const int j    = tid & 31;
    const int s    = tid >> 5;

    for (int idx = tid; idx < 128 * 64; idx += 128) {
        int rr = idx >> 6;
        int k4 = idx & 63;
        int q = rr >> 5, jj = rr & 31;
        float4 v = *(const float4*)&w_hh[(size_t)((q << 8) + u0 + jj) * Hc + (k4 << 2)];
        *(float4*)&wsh[rr * WSH_STRIDE + (k4 << 2)] = v;
    }
    for (int idx = tid; idx < 16 * 64; idx += 128) {
        int row = idx >> 6, k4 = idx & 63;
        *(float4*)&hb0[row * 256 + (k4 << 2)] =
            *(const float4*)&hxs[(size_t)(b0 + row) * Hc + (k4 << 2)];
    }

    // hoisted mapa: remote base addresses of hb0/hb1 in every cluster rank
    unsigned rb0[8], rb1[8];
    {
        unsigned a0 = (unsigned)__cvta_generic_to_shared(hb0);
        unsigned a1 = (unsigned)__cvta_generic_to_shared(hb1);
        #pragma unroll
        for (int rk = 0; rk < 8; ++rk) {
            asm volatile("mapa.shared::cluster.u32 %0, %1, %2;" : "=r"(rb0[rk]) : "r"(a0), "r"(rk));
            asm volatile("mapa.shared::cluster.u32 %0, %1, %2;" : "=r"(rb1[rk]) : "r"(a1), "r"(rk));
        }
    }

    int   gr[4]; int ro[4]; unsigned po[4];
    float c[4], hp[4];
    #pragma unroll
    for (int i = 0; i < 4; ++i) {
        int row = s + 4 * i;
        gr[i] = b0 + row;
        ro[i] = row * 256;
        po[i] = (unsigned)((row * 256 + u0 + j) * 4);
        c[i]  = cxs[(size_t)gr[i] * Hc + u0 + j];
        hp[i] = 0.0f;
    }
    float ar = 0.0f, tar = 0.0f;
    __syncthreads();

    const float* w0 = &wsh[(0 * 32 + j) * WSH_STRIDE];
    const float* w1 = &wsh[(1 * 32 + j) * WSH_STRIDE];
    const float* w2 = &wsh[(2 * 32 + j) * WSH_STRIDE];
    const float* w3 = &wsh[(3 * 32 + j) * WSH_STRIDE];

    // prefetch g_pre for t=0
    float pre[4][4];
    #pragma unroll
    for (int i = 0; i < 4; ++i) {
        const float* pr = &g_pre[(size_t)(gr[i] * Tc) * (4 * Hc) + u0 + j];
        pre[i][0] = pr[0];   pre[i][1] = pr[256];
        pre[i][2] = pr[512]; pre[i][3] = pr[768];
    }

    int cur = 0;
    for (int t = 0; t < Tc; ++t) {
        const float* hc = cur ? hb1 : hb0;
        const unsigned* rb = cur ? rb0 : rb1;   // hn = cur ? hb0 : hb1

        float acc[4][4];
        #pragma unroll
        for (int i = 0; i < 4; ++i) {
            acc[i][0] = pre[i][0]; acc[i][1] = pre[i][1];
            acc[i][2] = pre[i][2]; acc[i][3] = pre[i][3];
        }
        // prefetch next step's pre while the matvec runs
        if (t + 1 < Tc) {
            #pragma unroll
            for (int i = 0; i < 4; ++i) {
                const float* pr = &g_pre[(size_t)(gr[i] * Tc + t + 1) * (4 * Hc) + u0 + j];
                pre[i][0] = pr[0];   pre[i][1] = pr[256];
                pre[i][2] = pr[512]; pre[i][3] = pr[768];
            }
        }

        #pragma unroll 4
        for (int k4 = 0; k4 < 64; ++k4) {
            const int k = k4 << 2;
            float4 a = *(const float4*)&w0[k];
            float4 b = *(const float4*)&w1[k];
            float4 g = *(const float4*)&w2[k];
            float4 o = *(const float4*)&w3[k];
            #pragma unroll
            for (int i = 0; i < 4; ++i) {
                float4 h4 = *(const float4*)&hc[ro[i] + k];
                acc[i][0] = fmaf(h4.x, a.x, acc[i][0]);
                acc[i][0] = fmaf(h4.y, a.y, acc[i][0]);
                acc[i][0] = fmaf(h4.z, a.z, acc[i][0]);
                acc[i][0] = fmaf(h4.w, a.w, acc[i][0]);
                acc[i][1] = fmaf(h4.x, b.x, acc[i][1]);
                acc[i][1] = fmaf(h4.y, b.y, acc[i][1]);
                acc[i][1] = fmaf(h4.z, b.z, acc[i][1]);
                acc[i][1] = fmaf(h4.w, b.w, acc[i][1]);
                acc[i][2] = fmaf(h4.x, g.x, acc[i][2]);
                acc[i][2] = fmaf(h4.y, g.y, acc[i][2]);
                acc[i][2] = fmaf(h4.z, g.z, acc[i][2]);
                acc[i][2] = fmaf(h4.w, g.w, acc[i][2]);
                acc[i][3] = fmaf(h4.x, o.x, acc[i][3]);
                acc[i][3] = fmaf(h4.y, o.y, acc[i][3]);
                acc[i][3] = fmaf(h4.z, o.z, acc[i][3]);
                acc[i][3] = fmaf(h4.w, o.w, acc[i][3]);
            }
        }

        #pragma unroll
        for (int i = 0; i < 4; ++i) {
            float iv = sigm(acc[i][0]);
            float fv = sigm(acc[i][1]);
            float gv = tanh_f(acc[i][2]);
            float ov = sigm(acc[i][3]);
            float c2 = fmaf(fv, c[i], iv * gv);
            float h2 = ov * tanh_f(c2);
            c[i] = c2;
            ar = fmaf(h2, h2, ar);
            float d = h2 - hp[i];
            if (t > 0) tar = fmaf(d, d, tar);
            hp[i] = h2;

            const size_t base = (size_t)(gr[i] * Tc + t) * Hc + u0 + j;
            __stcs(&out[OFF_I  + base], iv);
            __stcs(&out[OFF_Fg + base], fv);
            __stcs(&out[OFF_Gg + base], gv);
            __stcs(&out[OFF_Og + base], ov);
            __stcs(&out[OFF_CS + base], c2);
            __stcs(&out[OFF_HS + base], h2);
            if (t == Tc - 1) {
                out[OFF_HT + (size_t)gr[i] * Hc + u0 + j] = h2;
                out[OFF_CT + (size_t)gr[i] * Hc + u0 + j] = c2;
            }
            #pragma unroll
            for (int rk = 0; rk < 8; ++rk) {
                asm volatile("st.shared::cluster.f32 [%0], %1;"
                             :: "r"(rb[rk] + po[i]), "f"(h2));
            }
        }

        cluster_sync_();
        cur ^= 1;
    }

    __shared__ float red[128];
    red[tid] = ar; __syncthreads();
    for (int o = 64; o > 0; o >>= 1) { if (tid < o) red[tid] += red[tid + o]; __syncthreads(); }
    if (tid == 0) g_part[blockIdx.x] = red[0];
    __syncthreads();
    red[tid] = tar; __syncthreads();
    for (int o = 64; o > 0; o >>= 1) { if (tid < o) red[tid] += red[tid + o]; __syncthreads(); }
    if (tid == 0) g_part[128 + blockIdx.x] = red[0];
}

// ---------------------------------------------------------------------------
// loss finalize
// ---------------------------------------------------------------------------
__global__ void loss_fin(float* __restrict__ out)
{
    __shared__ float r[128];
    int tid = threadIdx.x;
    r[tid] = g_part[tid]; __syncthreads();
    for (int o = 64; o > 0; o >>= 1) { if (tid < o) r[tid] += r[tid + o]; __syncthreads(); }
    float sar = r[0]; __syncthreads();
    r[tid] = g_part[128 + tid]; __syncthreads();
    for (int o = 64; o > 0; o >>= 1) { if (tid < o) r[tid] += r[tid + o]; __syncthreads(); }
    if (tid == 0) {
        out[OFF_AR]  = sar * (0.01f / 16777216.0f);
        out[OFF_TAR] = r[0] * (0.01f / 16711680.0f);
    }
}

// ---------------------------------------------------------------------------
// actor/critic heads
// ---------------------------------------------------------------------------
__global__ __launch_bounds__(256)
void head_kernel(const float* __restrict__ aw, const float* __restrict__ ab,
                 const float* __restrict__ cw, const float* __restrict__ cb,
                 float* __restrict__ out)
{
    __shared__ float ws[19 * 256];
    const int tid = threadIdx.x;
    for (int i = tid; i < Ac * Hc; i += 256) ws[i] = aw[i];
    for (int i = tid; i < Hc; i += 256) ws[Ac * Hc + i] = cw[i];
    __syncthreads();

    const int warp = tid >> 5, lane = tid & 31;
    const size_t m = (size_t)blockIdx.x * 8 + warp;
    const float* h = &out[OFF_HS + m * Hc];

    float p[19];
    #pragma unroll
    for (int o = 0; o < 19; ++o) p[o] = 0.0f;
    #pragma unroll
    for (int kk = 0; kk < 8; ++kk) {
        int k = lane + kk * 32;
        float hv = h[k];
        #pragma unroll
        for (int o = 0; o < 19; ++o) p[o] = fmaf(hv, ws[o * 256 + k], p[o]);
    }
    #pragma unroll
    for (int o = 0; o < 19; ++o)
        #pragma unroll
        for (int off = 16; off > 0; off >>= 1)
            p[o] += __shfl_down_sync(0xffffffffu, p[o], off);

    if (lane == 0) {
        #pragma unroll
        for (int o = 0; o < Ac; ++o)
            out[OFF_LOGITS + m * Ac + o] = p[o] + ab[o];
        out[OFF_VALUES + m] = p[18] + cb[0];
    }
}

// ---------------------------------------------------------------------------
// launcher
// ---------------------------------------------------------------------------
extern "C" void kernel_launch(void* const* d_in, const int* in_sizes, int n_in,
                              void* d_out, int out_size)
{
    const float* obs    = (const float*)d_in[0];
    const float* hxs    = (const float*)d_in[1];
    const float* cxs    = (const float*)d_in[2];
    const float* enc_w1 = (const float*)d_in[3];
    const float* enc_b1 = (const float*)d_in[4];
    const float* enc_w2 = (const float*)d_in[5];
    const float* enc_b2 = (const float*)d_in[6];
    const float* w_ih   = (const float*)d_in[7];
    const float* w_hh   = (const float*)d_in[8];
    const float* b_ih   = (const float*)d_in[9];
    const float* b_hh   = (const float*)d_in[10];
    const float* aw     = (const float*)d_in[11];
    const float* ab     = (const float*)d_in[12];
    const float* cw     = (const float*)d_in[13];
    const float* cb     = (const float*)d_in[14];
    float* out = (float*)d_out;

    void *p_pre, *p_bias;
    void *p_oh, *p_ol, *p_e1h, *p_e1l, *p_e2h, *p_e2l;
    void *p_w1h, *p_w2h, *p_wihh;
    cudaGetSymbolAddress(&p_pre,  g_pre);
    cudaGetSymbolAddress(&p_bias, g_bias);
    cudaGetSymbolAddress(&p_oh,   g_obs_h);  cudaGetSymbolAddress(&p_ol,   g_obs_l);
    cudaGetSymbolAddress(&p_e1h,  g_e1h);    cudaGetSymbolAddress(&p_e1l,  g_e1l);
    cudaGetSymbolAddress(&p_e2h,  g_e2h);    cudaGetSymbolAddress(&p_e2l,  g_e2l);
    cudaGetSymbolAddress(&p_w1h,  g_w1h);
    cudaGetSymbolAddress(&p_w2h,  g_w2h);
    cudaGetSymbolAddress(&p_wihh, g_wih_h);

    cudaFuncSetAttribute(lstm_kernel,
                         cudaFuncAttributeMaxDynamicSharedMemorySize, LSTM_SMEM);
    cudaFuncSetAttribute(gemm_mma,
                         cudaFuncAttributeMaxDynamicSharedMemorySize, GEMM_SMEM_TOT);

    const int M = Bc * Tc;  // 65536

    // fp16 planes: activations hi/lo, weights hi only
    {
        int n;
        n = M * Dc;      conv_split_h<<<(n + 255) / 256, 256>>>(obs, (__half*)p_oh, (__half*)p_ol, n);
        n = Ec * Dc;     conv_h<<<(n + 255) / 256, 256>>>(enc_w1, (__half*)p_w1h, n);
        n = Ec * Ec;     conv_h<<<(n + 255) / 256, 256>>>(enc_w2, (__half*)p_w2h, n);
        n = 4 * Hc * Ec; conv_h<<<(n + 255) / 256, 256>>>(w_ih,   (__half*)p_wihh, n);
    }
    prep_bias<<<1, 1024>>>(b_ih, b_hh);

    // enc1 = silu(obs @ w1^T + b1) -> fp16 hi/lo planes   (K=128, N=256)
    gemm_mma<<<dim3(M / 128, Ec / 128), 256, GEMM_SMEM_TOT>>>(
        (const __half*)p_oh, (const __half*)p_ol, (const __half*)p_w1h,
        enc_b1, nullptr, (__half*)p_e1h, (__half*)p_e1l, Dc, Ec, 1);
    // enc2 = silu(enc1 @ w2^T + b2) -> fp16 hi/lo planes  (K=256, N=256)
    gemm_mma<<<dim3(M / 128, Ec / 128), 256, GEMM_SMEM_TOT>>>(
        (const __half*)p_e1h, (const __half*)p_e1l, (const __half*)p_w2h,
        enc_b2, nullptr, (__half*)p_e2h, (__half*)p_e2l, Ec, Ec, 1);
    // pre = enc2 @ w_ih^T + (b_ih + b_hh) -> fp32         (K=256, N=1024)
    gemm_mma<<<dim3(M / 128, (4 * Hc) / 128), 256, GEMM_SMEM_TOT>>>(
        (const __half*)p_e2h, (const __half*)p_e2l, (const __half*)p_wihh,
        (const float*)p_bias, (float*)p_pre, nullptr, nullptr, Ec, 4 * Hc, 0);

    // persistent cluster LSTM
    lstm_kernel<<<128, 128, LSTM_SMEM>>>(hxs, cxs, w_hh, out);
    // losses
    loss_fin<<<1, 128>>>(out);
    // heads
    head_kernel<<<M / 8, 256>>>(aw, ab, cw, cb, out);
}

// round 9
// speedup vs baseline: 1.5990x; 1.1903x over previous
#include <cuda_runtime.h>
#include <cuda_fp16.h>
#include <cstdint>
#include <cstddef>

// ---------------------------------------------------------------------------
// Problem dims
// ---------------------------------------------------------------------------
#define Bc 256
#define Tc 256
#define Dc 128
#define Ec 256
#define Hc 256
#define Ac 18

static constexpr size_t N_LOGITS = (size_t)Bc * Tc * Ac;
static constexpr size_t NGATE    = (size_t)Bc * Tc * Hc;
static constexpr size_t OFF_LOGITS = 0;
static constexpr size_t OFF_VALUES = OFF_LOGITS + N_LOGITS;
static constexpr size_t OFF_HT     = OFF_VALUES + (size_t)Bc * Tc;
static constexpr size_t OFF_CT     = OFF_HT + (size_t)Bc * Hc;
static constexpr size_t OFF_AR     = OFF_CT + (size_t)Bc * Hc;
static constexpr size_t OFF_TAR    = OFF_AR + 1;
static constexpr size_t OFF_I      = OFF_TAR + 1;
static constexpr size_t OFF_Fg     = OFF_I + NGATE;
static constexpr size_t OFF_Gg     = OFF_Fg + NGATE;
static constexpr size_t OFF_Og     = OFF_Gg + NGATE;
static constexpr size_t OFF_CS     = OFF_Og + NGATE;
static constexpr size_t OFF_HS     = OFF_CS + NGATE;

// ---------------------------------------------------------------------------
// Device scratch
// ---------------------------------------------------------------------------
__device__ float  g_pre [(size_t)Bc * Tc * 4 * Hc];
__device__ float  g_bias[4 * Hc];
__device__ float  g_part[256];
__device__ __half g_obs_h[(size_t)Bc * Tc * Dc];
__device__ __half g_obs_l[(size_t)Bc * Tc * Dc];
__device__ __half g_e1h[(size_t)Bc * Tc * Ec];
__device__ __half g_e1l[(size_t)Bc * Tc * Ec];
__device__ __half g_e2h[(size_t)Bc * Tc * Ec];
__device__ __half g_e2l[(size_t)Bc * Tc * Ec];
__device__ __half g_w1h[Ec * Dc];
__device__ __half g_w2h[Ec * Ec];
__device__ __half g_wih_h[4 * Hc * Ec];

extern __shared__ __align__(1024) char dynsmem[];

// ---------------------------------------------------------------------------
// Math helpers
// ---------------------------------------------------------------------------
__device__ __forceinline__ float sigm(float x) {
    return __fdividef(1.0f, 1.0f + __expf(-x));
}
__device__ __forceinline__ float tanh_f(float x) {
    return 1.0f - __fdividef(2.0f, __expf(2.0f * x) + 1.0f);
}
__device__ __forceinline__ float silu(float x) { return x * sigm(x); }

__device__ __forceinline__ uint32_t smem_u32(const void* p) {
    uint32_t a;
    asm("{ .reg .u64 t; cvta.to.shared.u64 t, %1; cvt.u32.u64 %0, t; }" : "=r"(a) : "l"(p));
    return a;
}

// ---------------------------------------------------------------------------
// warp-MMA + cp.async primitives (baseline PTX, valid at target sm_100)
// ---------------------------------------------------------------------------
__device__ __forceinline__ void ldsm4(uint32_t* r, uint32_t addr) {
    asm volatile("ldmatrix.sync.aligned.m8n8.x4.shared.b16 {%0,%1,%2,%3}, [%4];"
                 : "=r"(r[0]), "=r"(r[1]), "=r"(r[2]), "=r"(r[3]) : "r"(addr));
}
__device__ __forceinline__ void ldsm2(uint32_t* r, uint32_t addr) {
    asm volatile("ldmatrix.sync.aligned.m8n8.x2.shared.b16 {%0,%1}, [%2];"
                 : "=r"(r[0]), "=r"(r[1]) : "r"(addr));
}
__device__ __forceinline__ void mma16816h(float* d, const uint32_t* a, const uint32_t* b) {
    asm volatile("mma.sync.aligned.m16n8k16.row.col.f32.f16.f16.f32 "
                 "{%0,%1,%2,%3}, {%4,%5,%6,%7}, {%8,%9}, {%0,%1,%2,%3};"
                 : "+f"(d[0]), "+f"(d[1]), "+f"(d[2]), "+f"(d[3])
                 : "r"(a[0]), "r"(a[1]), "r"(a[2]), "r"(a[3]), "r"(b[0]), "r"(b[1]));
}
__device__ __forceinline__ void cp16(uint32_t dst, const void* src) {
    asm volatile("cp.async.cg.shared.global [%0], [%1], 16;" :: "r"(dst), "l"(src));
}
#define CP_COMMIT() asm volatile("cp.async.commit_group;" ::: "memory")

// ---------------------------------------------------------------------------
// fp32 -> fp16 conversions
// ---------------------------------------------------------------------------
__global__ void conv_split_h(const float* __restrict__ in, __half* __restrict__ h,
                             __half* __restrict__ l, int n)
{
    int i = blockIdx.x * blockDim.x + threadIdx.x;
    if (i >= n) return;
    float x = in[i];
    __half hb = __float2half_rn(x);
    h[i] = hb;
    l[i] = __float2half_rn(x - __half2float(hb));
}
__global__ void conv_h(const float* __restrict__ in, __half* __restrict__ h, int n)
{
    int i = blockIdx.x * blockDim.x + threadIdx.x;
    if (i >= n) return;
    h[i] = __float2half_rn(in[i]);
}

// ---------------------------------------------------------------------------
// split-fp16 tensor-core GEMM (unchanged from R8 passing kernel)
// ---------------------------------------------------------------------------
#define PA_H 0
#define PA_L 10240
#define PB_H 20480
#define GSTAGE 30720
#define GDATA_OFF 512
#define GEMM_SMEM_TOT (GDATA_OFF + 2 * GSTAGE)

__device__ __forceinline__ void gemm_load_stage(
    uint32_t sbase,
    const __half* __restrict__ Ah, const __half* __restrict__ Al,
    const __half* __restrict__ Wh,
    int m0, int n0, int K, int k0, int tid)
{
    #pragma unroll
    for (int i = 0; i < 2; ++i) {
        int idx = tid + (i << 8);
        int row = idx >> 2, c = idx & 3;
        uint32_t d = (uint32_t)(row * 80 + c * 16);
        size_t ga = (size_t)(m0 + row) * K + k0 + c * 8;
        size_t gb = (size_t)(n0 + row) * K + k0 + c * 8;
        cp16(sbase + PA_H + d, Ah + ga);
        cp16(sbase + PA_L + d, Al + ga);
        cp16(sbase + PB_H + d, Wh + gb);
    }
}

__global__ __launch_bounds__(256)
void gemm_mma(const __half* __restrict__ Ah, const __half* __restrict__ Al,
              const __half* __restrict__ Wh,
              const float* __restrict__ bias, float* __restrict__ outF,
              __half* __restrict__ outH, __half* __restrict__ outL,
              int K, int N, int mode)
{
    const uint32_t sb = smem_u32(dynsmem);
    float* sbias = (float*)dynsmem;

    const int tid  = threadIdx.x;
    const int lane = tid & 31;
    const int w    = tid >> 5;
    const int wm   = w >> 2;
    const int wn   = w & 3;
    const int m0   = blockIdx.x * 128;
    const int n0   = blockIdx.y * 128;

    if (tid < 128) sbias[tid] = bias[n0 + tid];

    const int aro  = (lane & 7) + ((lane >> 3) & 1) * 8;
    const int ac16 = (lane >> 4) & 1;
    const int bl8  = lane & 15;
    const int bro  = bl8 & 7;
    const int bc16 = (bl8 >> 3) & 1;

    const uint32_t aBase = (uint32_t)aro * 80 + ac16 * 16;
    const uint32_t bBase = (uint32_t)bro * 80 + bc16 * 16;

    float acc[4][4][4];
    #pragma unroll
    for (int mt = 0; mt < 4; ++mt)
        #pragma unroll
        for (int nt = 0; nt < 4; ++nt)
            #pragma unroll
            for (int r = 0; r < 4; ++r) acc[mt][nt][r] = 0.0f;

    const int NCH = K >> 5;
    gemm_load_stage(sb + GDATA_OFF, Ah, Al, Wh, m0, n0, K, 0, tid);
    CP_COMMIT();

    for (int ch = 0; ch < NCH; ++ch) {
        if (ch + 1 < NCH) {
            gemm_load_stage(sb + GDATA_OFF + ((ch + 1) & 1) * GSTAGE,
                            Ah, Al, Wh, m0, n0, K, (ch + 1) << 5, tid);
            CP_COMMIT();
            asm volatile("cp.async.wait_group 1;" ::: "memory");
        } else {
            asm volatile("cp.async.wait_group 0;" ::: "memory");
        }
        __syncthreads();

        const uint32_t st = sb + GDATA_OFF + (ch & 1) * GSTAGE;
        #pragma unroll
        for (int ks = 0; ks < 2; ++ks) {
            uint32_t bh[4][2];
            #pragma unroll
            for (int nt = 0; nt < 4; ++nt) {
                uint32_t o = bBase + (uint32_t)(wn * 32 + nt * 8) * 80 + ks * 32;
                ldsm2(bh[nt], st + PB_H + o);
            }
            #pragma unroll
            for (int mt = 0; mt < 4; ++mt) {
                uint32_t ah[4], al[4];
                uint32_t o = aBase + (uint32_t)(wm * 64 + mt * 16) * 80 + ks * 32;
                ldsm4(ah, st + PA_H + o);
                ldsm4(al, st + PA_L + o);
                #pragma unroll
                for (int nt = 0; nt < 4; ++nt) {
                    mma16816h(acc[mt][nt], ah, bh[nt]);
                    mma16816h(acc[mt][nt], al, bh[nt]);
                }
            }
        }
        __syncthreads();
    }

    #pragma unroll
    for (int mt = 0; mt < 4; ++mt) {
        const int r0 = m0 + wm * 64 + mt * 16 + (lane >> 2);
        #pragma unroll
        for (int nt = 0; nt < 4; ++nt) {
            const int cl = wn * 32 + nt * 8 + (lane & 3) * 2;
            const int c  = n0 + cl;
            float v0 = acc[mt][nt][0] + sbias[cl];
            float v1 = acc[mt][nt][1] + sbias[cl + 1];
            float v2 = acc[mt][nt][2] + sbias[cl];
            float v3 = acc[mt][nt][3] + sbias[cl + 1];
            if (mode == 0) {
                *(float2*)&outF[(size_t)r0 * N + c]       = make_float2(v0, v1);
                *(float2*)&outF[(size_t)(r0 + 8) * N + c] = make_float2(v2, v3);
            } else {
                v0 = silu(v0); v1 = silu(v1); v2 = silu(v2); v3 = silu(v3);
                __half h0 = __float2half_rn(v0), h1 = __float2half_rn(v1);
                __half h2 = __float2half_rn(v2), h3 = __float2half_rn(v3);
                __half l0 = __float2half_rn(v0 - __half2float(h0));
                __half l1 = __float2half_rn(v1 - __half2float(h1));
                __half l2 = __float2half_rn(v2 - __half2float(h2));
                __half l3 = __float2half_rn(v3 - __half2float(h3));
                size_t o0 = (size_t)r0 * N + c, o1 = (size_t)(r0 + 8) * N + c;
                *(__half2*)&outH[o0] = __halves2half2(h0, h1);
                *(__half2*)&outL[o0] = __halves2half2(l0, l1);
                *(__half2*)&outH[o1] = __halves2half2(h2, h3);
                *(__half2*)&outL[o1] = __halves2half2(l2, l3);
            }
        }
    }
}

// ---------------------------------------------------------------------------
// bias prep
// ---------------------------------------------------------------------------
__global__ void prep_bias(const float* __restrict__ bih, const float* __restrict__ bhh)
{
    int i = threadIdx.x;
    g_bias[i] = bih[i] + bhh[i];
}

// ---------------------------------------------------------------------------
// Tensor-core persistent cluster LSTM.
// Cluster of 8 CTAs x 128 threads: cluster owns 16 batch rows; rank owns 32
// hidden units (gates interleaved unit-major: B row n = unit*4 + gate).
// Per step: gates[16x128] = h[16x256] @ Whh_slice^T via 3-pass split-fp16 MMA.
// h exchanged as fp16 hi/lo planes via st.shared::cluster, double-buffered.
// ---------------------------------------------------------------------------
__device__ __forceinline__ void cluster_sync_()
{
    asm volatile("barrier.cluster.arrive.aligned;" ::: "memory");
    asm volatile("barrier.cluster.wait.aligned;"   ::: "memory");
}

#define HSTR  264                        // halves per row (528 B rows, conflict-free ldmatrix)
#define SM_BH 0                          // Whh hi  [128][HSTR]
#define SM_BL (128 * HSTR * 2)           // Whh lo  [128][HSTR]        (67584)
#define SM_A0 (2 * 128 * HSTR * 2)       // h buf0: hi[16][HSTR], lo[16][HSTR]  (135168)
#define ABUF  (2 * 16 * HSTR * 2)        // 16896 per buffer
#define SM_A1 (SM_A0 + ABUF)             // 152064
#define SM_STG (SM_A1 + ABUF)            // staging hi[16][32], lo[16][32]  (168960)
#define LSTM_SMEM (SM_STG + 2 * 16 * 32 * 2)   // 171008

__global__ void __cluster_dims__(8, 1, 1) __launch_bounds__(128, 1)
lstm_kernel(const float* __restrict__ hxs, const float* __restrict__ cxs,
            const float* __restrict__ w_hh, float* __restrict__ out)
{
    char* smc = dynsmem;
    const uint32_t sb = smem_u32(dynsmem);
    const int tid  = threadIdx.x;
    const int lane = tid & 31;
    const int w    = tid >> 5;
    const int grp  = blockIdx.x >> 3;
    const int rank = blockIdx.x & 7;
    const int b0   = grp * 16;
    const int u0   = rank * 32;

    // ---- fill Whh hi/lo planes: row n = lu*4 + q  <-  w_hh[q*256 + u0 + lu][:]
    {
        int lu = tid >> 2, q = tid & 3;
        const float* src = &w_hh[(size_t)((q << 8) + u0 + lu) * Hc];
        __half* bh = (__half*)(smc + SM_BH) + tid * HSTR;
        __half* bl = (__half*)(smc + SM_BL) + tid * HSTR;
        for (int k = 0; k < Hc; k += 4) {
            float4 v = *(const float4*)&src[k];
            __half h0 = __float2half_rn(v.x), h1 = __float2half_rn(v.y);
            __half h2 = __float2half_rn(v.z), h3 = __float2half_rn(v.w);
            bh[k + 0] = h0; bh[k + 1] = h1; bh[k + 2] = h2; bh[k + 3] = h3;
            bl[k + 0] = __float2half_rn(v.x - __half2float(h0));
            bl[k + 1] = __float2half_rn(v.y - __half2float(h1));
            bl[k + 2] = __float2half_rn(v.z - __half2float(h2));
            bl[k + 3] = __float2half_rn(v.w - __half2float(h3));
        }
    }
    // ---- init h buffer 0 from hxs (full 16x256, hi/lo planes)
    for (int idx = tid; idx < 16 * 64; idx += 128) {
        int row = idx >> 6, k4 = (idx & 63) << 2;
        float4 v = *(const float4*)&hxs[(size_t)(b0 + row) * Hc + k4];
        __half* ah = (__half*)(smc + SM_A0) + row * HSTR + k4;
        __half* al = (__half*)(smc + SM_A0 + ABUF / 2) + row * HSTR + k4;
        __half h0 = __float2half_rn(v.x), h1 = __float2half_rn(v.y);
        __half h2 = __float2half_rn(v.z), h3 = __float2half_rn(v.w);
        ah[0] = h0; ah[1] = h1; ah[2] = h2; ah[3] = h3;
        al[0] = __float2half_rn(v.x - __half2float(h0));
        al[1] = __float2half_rn(v.y - __half2float(h1));
        al[2] = __float2half_rn(v.z - __half2float(h2));
        al[3] = __float2half_rn(v.w - __half2float(h3));
    }

    // mapa: remote A-buffer bases for all 8 ranks
    unsigned ra0[8], ra1[8];
    {
        unsigned a0 = sb + SM_A0, a1 = sb + SM_A1;
        #pragma unroll
        for (int rk = 0; rk < 8; ++rk) {
            asm volatile("mapa.shared::cluster.u32 %0, %1, %2;" : "=r"(ra0[rk]) : "r"(a0), "r"(rk));
            asm volatile("mapa.shared::cluster.u32 %0, %1, %2;" : "=r"(ra1[rk]) : "r"(a1), "r"(rk));
        }
    }

    // thread/cell geometry (R6-proven fragment layout)
    const int d_    = (lane & 3) >> 1;                 // unit parity within nsub
    const bool isT0 = ((lane & 1) == 0);               // holds (i,f); partner holds (g,o)
    const int r1    = lane >> 2;                       // frag row
    const int myrow = r1 + ((lane & 1) << 3);          // owned cell row
    const int q0    = (lane & 1) ? 2 : 0;              // first gate index in frag cols

    float c[4], hp[4];
    int lcs[4];
    #pragma unroll
    for (int s = 0; s < 4; ++s) {
        lcs[s] = 8 * w + 2 * s + d_;                   // local unit 0..31
        c[s]  = cxs[(size_t)(b0 + myrow) * Hc + u0 + lcs[s]];
        hp[s] = 0.0f;
    }
    float ar = 0.0f, tar = 0.0f;

    // ldmatrix per-lane address offset (rows 0..15 pattern, k-half select)
    const uint32_t aoff = (uint32_t)((lane & 7) + ((lane >> 3) & 1) * 8) * 528
                        + (uint32_t)((lane >> 4) & 1) * 16;
    const uint32_t bofs0 = (uint32_t)(32 * w) * 528 + aoff;        // nsub 0,1
    const uint32_t bofs1 = (uint32_t)(32 * w + 16) * 528 + aoff;   // nsub 2,3

    __half* stage_h = (__half*)(smc + SM_STG);
    __half* stage_l = (__half*)(smc + SM_STG + 1024);

    __syncthreads();

    // prefetch g_pre for t=0
    float pre[4][4];
    {
        size_t p1 = ((size_t)((b0 + r1) * Tc)) * 1024;
        size_t p2 = ((size_t)((b0 + r1 + 8) * Tc)) * 1024;
        #pragma unroll
        for (int s = 0; s < 4; ++s) {
            int col = q0 * 256 + u0 + lcs[s];
            pre[s][0] = g_pre[p1 + col]; pre[s][1] = g_pre[p1 + col + 256];
            pre[s][2] = g_pre[p2 + col]; pre[s][3] = g_pre[p2 + col + 256];
        }
    }

    int cur = 0;
    for (int t = 0; t < Tc; ++t) {
        float acc[4][4];
        #pragma unroll
        for (int s = 0; s < 4; ++s) {
            acc[s][0] = pre[s][0]; acc[s][1] = pre[s][1];
            acc[s][2] = pre[s][2]; acc[s][3] = pre[s][3];
        }
        if (t + 1 < Tc) {
            size_t p1 = ((size_t)((b0 + r1) * Tc + t + 1)) * 1024;
            size_t p2 = ((size_t)((b0 + r1 + 8) * Tc + t + 1)) * 1024;
            #pragma unroll
            for (int s = 0; s < 4; ++s) {
                int col = q0 * 256 + u0 + lcs[s];
                pre[s][0] = g_pre[p1 + col]; pre[s][1] = g_pre[p1 + col + 256];
                pre[s][2] = g_pre[p2 + col]; pre[s][3] = g_pre[p2 + col + 256];
            }
        }

        const uint32_t abh = sb + (cur ? SM_A1 : SM_A0);
        const uint32_t abl = abh + ABUF / 2;

        #pragma unroll 4
        for (int kc = 0; kc < 16; ++kc) {
            const uint32_t ko = (uint32_t)kc * 32;
            uint32_t ah[4], al[4], p0h[4], p1h[4], p0l[4], p1l[4];
            ldsm4(ah, abh + aoff + ko);
            ldsm4(al, abl + aoff + ko);
            ldsm4(p0h, sb + SM_BH + bofs0 + ko);
            ldsm4(p1h, sb + SM_BH + bofs1 + ko);
            ldsm4(p0l, sb + SM_BL + bofs0 + ko);
            ldsm4(p1l, sb + SM_BL + bofs1 + ko);
            // b-frags: nsub0={p0[0],p0[2]}, nsub1={p0[1],p0[3]}, nsub2={p1[0],p1[2]}, nsub3={p1[1],p1[3]}
            uint32_t bh[4][2] = {{p0h[0], p0h[2]}, {p0h[1], p0h[3]},
                                 {p1h[0], p1h[2]}, {p1h[1], p1h[3]}};
            uint32_t bl[4][2] = {{p0l[0], p0l[2]}, {p0l[1], p0l[3]},
                                 {p1l[0], p1l[2]}, {p1l[1], p1l[3]}};
            #pragma unroll
            for (int s = 0; s < 4; ++s) {
                mma16816h(acc[s], ah, bh[s]);
                mma16816h(acc[s], al, bh[s]);
                mma16816h(acc[s], ah, bl[s]);
            }
        }

        // pointwise cell: 2 shuffles assemble (i,f,g,o) per owned cell
        #pragma unroll
        for (int s = 0; s < 4; ++s) {
            float sh1 = __shfl_xor_sync(0xffffffffu, isT0 ? acc[s][2] : acc[s][0], 1);
            float sh2 = __shfl_xor_sync(0xffffffffu, isT0 ? acc[s][3] : acc[s][1], 1);
            float i_, f_, g_, o_;
            if (isT0) { i_ = acc[s][0]; f_ = acc[s][1]; g_ = sh1; o_ = sh2; }
            else      { g_ = acc[s][2]; o_ = acc[s][3]; i_ = sh1; f_ = sh2; }

            float iv = sigm(i_), fv = sigm(f_), gv = tanh_f(g_), ov = sigm(o_);
            float c2 = fmaf(fv, c[s], iv * gv);
            float h2 = ov * tanh_f(c2);
            c[s] = c2;
            ar = fmaf(h2, h2, ar);
            float dd = h2 - hp[s];
            if (t > 0) tar = fmaf(dd, dd, tar);
            hp[s] = h2;

            const int grow = b0 + myrow;
            const int unit = u0 + lcs[s];
            const size_t base = ((size_t)(grow * Tc + t)) * Hc + unit;
            __stcs(&out[OFF_I  + base], iv);
            __stcs(&out[OFF_Fg + base], fv);
            __stcs(&out[OFF_Gg + base], gv);
            __stcs(&out[OFF_Og + base], ov);
            __stcs(&out[OFF_CS + base], c2);
            __stcs(&out[OFF_HS + base], h2);
            if (t == Tc - 1) {
                out[OFF_HT + (size_t)grow * Hc + unit] = h2;
                out[OFF_CT + (size_t)grow * Hc + unit] = c2;
            }
            __half hh = __float2half_rn(h2);
            stage_h[myrow * 32 + lcs[s]] = hh;
            stage_l[myrow * 32 + lcs[s]] = __float2half_rn(h2 - __half2float(hh));
        }

        __syncthreads();

        // push own 32-unit h chunk (hi+lo planes) to all 8 ranks' next buffer
        {
            const int p   = tid >> 6;          // plane
            const int rem = tid & 63;
            const int row = rem >> 2;
            const int ch  = rem & 3;           // 8-unit chunk
            uint4 v = *(const uint4*)(smc + SM_STG + p * 1024 + (row * 32 + ch * 8) * 2);
            const uint32_t dsto = (uint32_t)p * (ABUF / 2) + (uint32_t)row * 528
                                + (uint32_t)(u0 + ch * 8) * 2;
            const unsigned* rbuf = cur ? ra0 : ra1;   // write buffer cur^1
            #pragma unroll
            for (int rk = 0; rk < 8; ++rk) {
                asm volatile("st.shared::cluster.v4.b32 [%0], {%1,%2,%3,%4};"
                             :: "r"(rbuf[rk] + dsto), "r"(v.x), "r"(v.y), "r"(v.z), "r"(v.w)
                             : "memory");
            }
        }

        cluster_sync_();
        cur ^= 1;
    }

    __shared__ float red[128];
    red[tid] = ar; __syncthreads();
    for (int o = 64; o > 0; o >>= 1) { if (tid < o) red[tid] += red[tid + o]; __syncthreads(); }
    if (tid == 0) g_part[blockIdx.x] = red[0];
    __syncthreads();
    red[tid] = tar; __syncthreads();
    for (int o = 64; o > 0; o >>= 1) { if (tid < o) red[tid] += red[tid + o]; __syncthreads(); }
    if (tid == 0) g_part[128 + blockIdx.x] = red[0];
}

// ---------------------------------------------------------------------------
// loss finalize
// ---------------------------------------------------------------------------
__global__ void loss_fin(float* __restrict__ out)
{
    __shared__ float r[128];
    int tid = threadIdx.x;
    r[tid] = g_part[tid]; __syncthreads();
    for (int o = 64; o > 0; o >>= 1) { if (tid < o) r[tid] += r[tid + o]; __syncthreads(); }
    float sar = r[0]; __syncthreads();
    r[tid] = g_part[128 + tid]; __syncthreads();
    for (int o = 64; o > 0; o >>= 1) { if (tid < o) r[tid] += r[tid + o]; __syncthreads(); }
    if (tid == 0) {
        out[OFF_AR]  = sar * (0.01f / 16777216.0f);
        out[OFF_TAR] = r[0] * (0.01f / 16711680.0f);
    }
}

// ---------------------------------------------------------------------------
// actor/critic heads
// ---------------------------------------------------------------------------
__global__ __launch_bounds__(256)
void head_kernel(const float* __restrict__ aw, const float* __restrict__ ab,
                 const float* __restrict__ cw, const float* __restrict__ cb,
                 float* __restrict__ out)
{
    __shared__ float ws[19 * 256];
    const int tid = threadIdx.x;
    for (int i = tid; i < Ac * Hc; i += 256) ws[i] = aw[i];
    for (int i = tid; i < Hc; i += 256) ws[Ac * Hc + i] = cw[i];
    __syncthreads();

    const int warp = tid >> 5, lane = tid & 31;
    const size_t m = (size_t)blockIdx.x * 8 + warp;
    const float* h = &out[OFF_HS + m * Hc];

    float p[19];
    #pragma unroll
    for (int o = 0; o < 19; ++o) p[o] = 0.0f;
    #pragma unroll
    for (int kk = 0; kk < 8; ++kk) {
        int k = lane + kk * 32;
        float hv = h[k];
        #pragma unroll
        for (int o = 0; o < 19; ++o) p[o] = fmaf(hv, ws[o * 256 + k], p[o]);
    }
    #pragma unroll
    for (int o = 0; o < 19; ++o)
        #pragma unroll
        for (int off = 16; off > 0; off >>= 1)
            p[o] += __shfl_down_sync(0xffffffffu, p[o], off);

    if (lane == 0) {
        #pragma unroll
        for (int o = 0; o < Ac; ++o)
            out[OFF_LOGITS + m * Ac + o] = p[o] + ab[o];
        out[OFF_VALUES + m] = p[18] + cb[0];
    }
}

// ---------------------------------------------------------------------------
// launcher
// ---------------------------------------------------------------------------
extern "C" void kernel_launch(void* const* d_in, const int* in_sizes, int n_in,
                              void* d_out, int out_size)
{
    const float* obs    = (const float*)d_in[0];
    const float* hxs    = (const float*)d_in[1];
    const float* cxs    = (const float*)d_in[2];
    const float* enc_w1 = (const float*)d_in[3];
    const float* enc_b1 = (const float*)d_in[4];
    const float* enc_w2 = (const float*)d_in[5];
    const float* enc_b2 = (const float*)d_in[6];
    const float* w_ih   = (const float*)d_in[7];
    const float* w_hh   = (const float*)d_in[8];
    const float* b_ih   = (const float*)d_in[9];
    const float* b_hh   = (const float*)d_in[10];
    const float* aw     = (const float*)d_in[11];
    const float* ab     = (const float*)d_in[12];
    const float* cw     = (const float*)d_in[13];
    const float* cb     = (const float*)d_in[14];
    float* out = (float*)d_out;

    void *p_pre, *p_bias;
    void *p_oh, *p_ol, *p_e1h, *p_e1l, *p_e2h, *p_e2l;
    void *p_w1h, *p_w2h, *p_wihh;
    cudaGetSymbolAddress(&p_pre,  g_pre);
    cudaGetSymbolAddress(&p_bias, g_bias);
    cudaGetSymbolAddress(&p_oh,   g_obs_h);  cudaGetSymbolAddress(&p_ol,   g_obs_l);
    cudaGetSymbolAddress(&p_e1h,  g_e1h);    cudaGetSymbolAddress(&p_e1l,  g_e1l);
    cudaGetSymbolAddress(&p_e2h,  g_e2h);    cudaGetSymbolAddress(&p_e2l,  g_e2l);
    cudaGetSymbolAddress(&p_w1h,  g_w1h);
    cudaGetSymbolAddress(&p_w2h,  g_w2h);
    cudaGetSymbolAddress(&p_wihh, g_wih_h);

    cudaFuncSetAttribute(lstm_kernel,
                         cudaFuncAttributeMaxDynamicSharedMemorySize, LSTM_SMEM);
    cudaFuncSetAttribute(gemm_mma,
                         cudaFuncAttributeMaxDynamicSharedMemorySize, GEMM_SMEM_TOT);

    const int M = Bc * Tc;  // 65536

    {
        int n;
        n = M * Dc;      conv_split_h<<<(n + 255) / 256, 256>>>(obs, (__half*)p_oh, (__half*)p_ol, n);
        n = Ec * Dc;     conv_h<<<(n + 255) / 256, 256>>>(enc_w1, (__half*)p_w1h, n);
        n = Ec * Ec;     conv_h<<<(n + 255) / 256, 256>>>(enc_w2, (__half*)p_w2h, n);
        n = 4 * Hc * Ec; conv_h<<<(n + 255) / 256, 256>>>(w_ih,   (__half*)p_wihh, n);
    }
    prep_bias<<<1, 1024>>>(b_ih, b_hh);

    gemm_mma<<<dim3(M / 128, Ec / 128), 256, GEMM_SMEM_TOT>>>(
        (const __half*)p_oh, (const __half*)p_ol, (const __half*)p_w1h,
        enc_b1, nullptr, (__half*)p_e1h, (__half*)p_e1l, Dc, Ec, 1);
    gemm_mma<<<dim3(M / 128, Ec / 128), 256, GEMM_SMEM_TOT>>>(
        (const __half*)p_e1h, (const __half*)p_e1l, (const __half*)p_w2h,
        enc_b2, nullptr, (__half*)p_e2h, (__half*)p_e2l, Ec, Ec, 1);
    gemm_mma<<<dim3(M / 128, (4 * Hc) / 128), 256, GEMM_SMEM_TOT>>>(
        (const __half*)p_e2h, (const __half*)p_e2l, (const __half*)p_wihh,
        (const float*)p_bias, (float*)p_pre, nullptr, nullptr, Ec, 4 * Hc, 0);

    lstm_kernel<<<128, 128, LSTM_SMEM>>>(hxs, cxs, w_hh, out);
    loss_fin<<<1, 128>>>(out);
    head_kernel<<<M / 8, 256>>>(aw, ab, cw, cb, out);
}

// round 10
// speedup vs baseline: 2.0686x; 1.2937x over previous
#include <cuda_runtime.h>
#include <cuda_fp16.h>
#include <cstdint>
#include <cstddef>

// ---------------------------------------------------------------------------
// Problem dims
// ---------------------------------------------------------------------------
#define Bc 256
#define Tc 256
#define Dc 128
#define Ec 256
#define Hc 256
#define Ac 18

static constexpr size_t N_LOGITS = (size_t)Bc * Tc * Ac;
static constexpr size_t NGATE    = (size_t)Bc * Tc * Hc;
static constexpr size_t OFF_LOGITS = 0;
static constexpr size_t OFF_VALUES = OFF_LOGITS + N_LOGITS;
static constexpr size_t OFF_HT     = OFF_VALUES + (size_t)Bc * Tc;
static constexpr size_t OFF_CT     = OFF_HT + (size_t)Bc * Hc;
static constexpr size_t OFF_AR     = OFF_CT + (size_t)Bc * Hc;
static constexpr size_t OFF_TAR    = OFF_AR + 1;
static constexpr size_t OFF_I      = OFF_TAR + 1;
static constexpr size_t OFF_Fg     = OFF_I + NGATE;
static constexpr size_t OFF_Gg     = OFF_Fg + NGATE;
static constexpr size_t OFF_Og     = OFF_Gg + NGATE;
static constexpr size_t OFF_CS     = OFF_Og + NGATE;
static constexpr size_t OFF_HS     = OFF_CS + NGATE;

// ---------------------------------------------------------------------------
// Device scratch
// ---------------------------------------------------------------------------
__device__ float  g_pre [(size_t)Bc * Tc * 4 * Hc];
__device__ float  g_bias[4 * Hc];
__device__ float  g_part[256];
__device__ __half g_obs_h[(size_t)Bc * Tc * Dc];
__device__ __half g_obs_l[(size_t)Bc * Tc * Dc];
__device__ __half g_e1h[(size_t)Bc * Tc * Ec];
__device__ __half g_e1l[(size_t)Bc * Tc * Ec];
__device__ __half g_e2h[(size_t)Bc * Tc * Ec];
__device__ __half g_e2l[(size_t)Bc * Tc * Ec];
__device__ __half g_w1h[Ec * Dc];
__device__ __half g_w2h[Ec * Ec];
__device__ __half g_wih_h[4 * Hc * Ec];

extern __shared__ __align__(1024) char dynsmem[];

// ---------------------------------------------------------------------------
// Math helpers
// ---------------------------------------------------------------------------
__device__ __forceinline__ float sigm(float x) {
    return __fdividef(1.0f, 1.0f + __expf(-x));
}
__device__ __forceinline__ float tanh_f(float x) {
    return 1.0f - __fdividef(2.0f, __expf(2.0f * x) + 1.0f);
}
__device__ __forceinline__ float silu(float x) { return x * sigm(x); }

__device__ __forceinline__ uint32_t smem_u32(const void* p) {
    uint32_t a;
    asm("{ .reg .u64 t; cvta.to.shared.u64 t, %1; cvt.u32.u64 %0, t; }" : "=r"(a) : "l"(p));
    return a;
}

// ---------------------------------------------------------------------------
// warp-MMA + cp.async primitives (baseline PTX, valid at target sm_100)
// ---------------------------------------------------------------------------
__device__ __forceinline__ void ldsm4(uint32_t* r, uint32_t addr) {
    asm volatile("ldmatrix.sync.aligned.m8n8.x4.shared.b16 {%0,%1,%2,%3}, [%4];"
                 : "=r"(r[0]), "=r"(r[1]), "=r"(r[2]), "=r"(r[3]) : "r"(addr));
}
__device__ __forceinline__ void ldsm2(uint32_t* r, uint32_t addr) {
    asm volatile("ldmatrix.sync.aligned.m8n8.x2.shared.b16 {%0,%1}, [%2];"
                 : "=r"(r[0]), "=r"(r[1]) : "r"(addr));
}
__device__ __forceinline__ void mma16816h(float* d, const uint32_t* a, const uint32_t* b) {
    asm volatile("mma.sync.aligned.m16n8k16.row.col.f32.f16.f16.f32 "
                 "{%0,%1,%2,%3}, {%4,%5,%6,%7}, {%8,%9}, {%0,%1,%2,%3};"
                 : "+f"(d[0]), "+f"(d[1]), "+f"(d[2]), "+f"(d[3])
                 : "r"(a[0]), "r"(a[1]), "r"(a[2]), "r"(a[3]), "r"(b[0]), "r"(b[1]));
}
__device__ __forceinline__ void cp16(uint32_t dst, const void* src) {
    asm volatile("cp.async.cg.shared.global [%0], [%1], 16;" :: "r"(dst), "l"(src));
}
#define CP_COMMIT() asm volatile("cp.async.commit_group;" ::: "memory")

// ---------------------------------------------------------------------------
// fp32 -> fp16 conversions
// ---------------------------------------------------------------------------
__global__ void conv_split_h(const float* __restrict__ in, __half* __restrict__ h,
                             __half* __restrict__ l, int n)
{
    int i = blockIdx.x * blockDim.x + threadIdx.x;
    if (i >= n) return;
    float x = in[i];
    __half hb = __float2half_rn(x);
    h[i] = hb;
    l[i] = __float2half_rn(x - __half2float(hb));
}
__global__ void conv_h(const float* __restrict__ in, __half* __restrict__ h, int n)
{
    int i = blockIdx.x * blockDim.x + threadIdx.x;
    if (i >= n) return;
    h[i] = __float2half_rn(in[i]);
}

// ---------------------------------------------------------------------------
// split-fp16 tensor-core GEMM (unchanged from R8/R9 passing kernel)
// ---------------------------------------------------------------------------
#define PA_H 0
#define PA_L 10240
#define PB_H 20480
#define GSTAGE 30720
#define GDATA_OFF 512
#define GEMM_SMEM_TOT (GDATA_OFF + 2 * GSTAGE)

__device__ __forceinline__ void gemm_load_stage(
    uint32_t sbase,
    const __half* __restrict__ Ah, const __half* __restrict__ Al,
    const __half* __restrict__ Wh,
    int m0, int n0, int K, int k0, int tid)
{
    #pragma unroll
    for (int i = 0; i < 2; ++i) {
        int idx = tid + (i << 8);
        int row = idx >> 2, c = idx & 3;
        uint32_t d = (uint32_t)(row * 80 + c * 16);
        size_t ga = (size_t)(m0 + row) * K + k0 + c * 8;
        size_t gb = (size_t)(n0 + row) * K + k0 + c * 8;
        cp16(sbase + PA_H + d, Ah + ga);
        cp16(sbase + PA_L + d, Al + ga);
        cp16(sbase + PB_H + d, Wh + gb);
    }
}

__global__ __launch_bounds__(256)
void gemm_mma(const __half* __restrict__ Ah, const __half* __restrict__ Al,
              const __half* __restrict__ Wh,
              const float* __restrict__ bias, float* __restrict__ outF,
              __half* __restrict__ outH, __half* __restrict__ outL,
              int K, int N, int mode)
{
    const uint32_t sb = smem_u32(dynsmem);
    float* sbias = (float*)dynsmem;

    const int tid  = threadIdx.x;
    const int lane = tid & 31;
    const int w    = tid >> 5;
    const int wm   = w >> 2;
    const int wn   = w & 3;
    const int m0   = blockIdx.x * 128;
    const int n0   = blockIdx.y * 128;

    if (tid < 128) sbias[tid] = bias[n0 + tid];

    const int aro  = (lane & 7) + ((lane >> 3) & 1) * 8;
    const int ac16 = (lane >> 4) & 1;
    const int bl8  = lane & 15;
    const int bro  = bl8 & 7;
    const int bc16 = (bl8 >> 3) & 1;

    const uint32_t aBase = (uint32_t)aro * 80 + ac16 * 16;
    const uint32_t bBase = (uint32_t)bro * 80 + bc16 * 16;

    float acc[4][4][4];
    #pragma unroll
    for (int mt = 0; mt < 4; ++mt)
        #pragma unroll
        for (int nt = 0; nt < 4; ++nt)
            #pragma unroll
            for (int r = 0; r < 4; ++r) acc[mt][nt][r] = 0.0f;

    const int NCH = K >> 5;
    gemm_load_stage(sb + GDATA_OFF, Ah, Al, Wh, m0, n0, K, 0, tid);
    CP_COMMIT();

    for (int ch = 0; ch < NCH; ++ch) {
        if (ch + 1 < NCH) {
            gemm_load_stage(sb + GDATA_OFF + ((ch + 1) & 1) * GSTAGE,
                            Ah, Al, Wh, m0, n0, K, (ch + 1) << 5, tid);
            CP_COMMIT();
            asm volatile("cp.async.wait_group 1;" ::: "memory");
        } else {
            asm volatile("cp.async.wait_group 0;" ::: "memory");
        }
        __syncthreads();

        const uint32_t st = sb + GDATA_OFF + (ch & 1) * GSTAGE;
        #pragma unroll
        for (int ks = 0; ks < 2; ++ks) {
            uint32_t bh[4][2];
            #pragma unroll
            for (int nt = 0; nt < 4; ++nt) {
                uint32_t o = bBase + (uint32_t)(wn * 32 + nt * 8) * 80 + ks * 32;
                ldsm2(bh[nt], st + PB_H + o);
            }
            #pragma unroll
            for (int mt = 0; mt < 4; ++mt) {
                uint32_t ah[4], al[4];
                uint32_t o = aBase + (uint32_t)(wm * 64 + mt * 16) * 80 + ks * 32;
                ldsm4(ah, st + PA_H + o);
                ldsm4(al, st + PA_L + o);
                #pragma unroll
                for (int nt = 0; nt < 4; ++nt) {
                    mma16816h(acc[mt][nt], ah, bh[nt]);
                    mma16816h(acc[mt][nt], al, bh[nt]);
                }
            }
        }
        __syncthreads();
    }

    #pragma unroll
    for (int mt = 0; mt < 4; ++mt) {
        const int r0 = m0 + wm * 64 + mt * 16 + (lane >> 2);
        #pragma unroll
        for (int nt = 0; nt < 4; ++nt) {
            const int cl = wn * 32 + nt * 8 + (lane & 3) * 2;
            const int c  = n0 + cl;
            float v0 = acc[mt][nt][0] + sbias[cl];
            float v1 = acc[mt][nt][1] + sbias[cl + 1];
            float v2 = acc[mt][nt][2] + sbias[cl];
            float v3 = acc[mt][nt][3] + sbias[cl + 1];
            if (mode == 0) {
                *(float2*)&outF[(size_t)r0 * N + c]       = make_float2(v0, v1);
                *(float2*)&outF[(size_t)(r0 + 8) * N + c] = make_float2(v2, v3);
            } else {
                v0 = silu(v0); v1 = silu(v1); v2 = silu(v2); v3 = silu(v3);
                __half h0 = __float2half_rn(v0), h1 = __float2half_rn(v1);
                __half h2 = __float2half_rn(v2), h3 = __float2half_rn(v3);
                __half l0 = __float2half_rn(v0 - __half2float(h0));
                __half l1 = __float2half_rn(v1 - __half2float(h1));
                __half l2 = __float2half_rn(v2 - __half2float(h2));
                __half l3 = __float2half_rn(v3 - __half2float(h3));
                size_t o0 = (size_t)r0 * N + c, o1 = (size_t)(r0 + 8) * N + c;
                *(__half2*)&outH[o0] = __halves2half2(h0, h1);
                *(__half2*)&outL[o0] = __halves2half2(l0, l1);
                *(__half2*)&outH[o1] = __halves2half2(h2, h3);
                *(__half2*)&outL[o1] = __halves2half2(l2, l3);
            }
        }
    }
}

// ---------------------------------------------------------------------------
// bias prep
// ---------------------------------------------------------------------------
__global__ void prep_bias(const float* __restrict__ bih, const float* __restrict__ bhh)
{
    int i = threadIdx.x;
    g_bias[i] = bih[i] + bhh[i];
}

// ---------------------------------------------------------------------------
// Tensor-core persistent cluster LSTM (2-pass split: h hi/lo x Whh hi).
// Gate stores + g_pre prefetch hidden inside cluster arrive->wait window.
// ---------------------------------------------------------------------------
#define HSTR  264
#define SM_BH 0                            // Whh hi [128][HSTR]       (67584 B)
#define SM_A0 (128 * HSTR * 2)             // h buf0: hi[16]+lo[16]    (67584)
#define ABUF  (2 * 16 * HSTR * 2)          // 16896 per buffer
#define SM_A1 (SM_A0 + ABUF)               // 84480
#define SM_STG (SM_A1 + ABUF)              // 101376
#define LSTM_SMEM (SM_STG + 2 * 16 * 32 * 2)   // 103424

__global__ void __cluster_dims__(8, 1, 1) __launch_bounds__(128, 1)
lstm_kernel(const float* __restrict__ hxs, const float* __restrict__ cxs,
            const float* __restrict__ w_hh, float* __restrict__ out)
{
    char* smc = dynsmem;
    const uint32_t sb = smem_u32(dynsmem);
    const int tid  = threadIdx.x;
    const int lane = tid & 31;
    const int w    = tid >> 5;
    const int grp  = blockIdx.x >> 3;
    const int rank = blockIdx.x & 7;
    const int b0   = grp * 16;
    const int u0   = rank * 32;

    // Whh hi plane: row n = lu*4 + q  <-  w_hh[q*256 + u0 + lu][:]
    {
        int lu = tid >> 2, q = tid & 3;
        const float* src = &w_hh[(size_t)((q << 8) + u0 + lu) * Hc];
        __half* bh = (__half*)(smc + SM_BH) + tid * HSTR;
        for (int k = 0; k < Hc; k += 4) {
            float4 v = *(const float4*)&src[k];
            bh[k + 0] = __float2half_rn(v.x);
            bh[k + 1] = __float2half_rn(v.y);
            bh[k + 2] = __float2half_rn(v.z);
            bh[k + 3] = __float2half_rn(v.w);
        }
    }
    // init h buffer 0 from hxs (hi/lo planes)
    for (int idx = tid; idx < 16 * 64; idx += 128) {
        int row = idx >> 6, k4 = (idx & 63) << 2;
        float4 v = *(const float4*)&hxs[(size_t)(b0 + row) * Hc + k4];
        __half* ah = (__half*)(smc + SM_A0) + row * HSTR + k4;
        __half* al = (__half*)(smc + SM_A0 + ABUF / 2) + row * HSTR + k4;
        __half h0 = __float2half_rn(v.x), h1 = __float2half_rn(v.y);
        __half h2 = __float2half_rn(v.z), h3 = __float2half_rn(v.w);
        ah[0] = h0; ah[1] = h1; ah[2] = h2; ah[3] = h3;
        al[0] = __float2half_rn(v.x - __half2float(h0));
        al[1] = __float2half_rn(v.y - __half2float(h1));
        al[2] = __float2half_rn(v.z - __half2float(h2));
        al[3] = __float2half_rn(v.w - __half2float(h3));
    }

    unsigned ra0[8], ra1[8];
    {
        unsigned a0 = sb + SM_A0, a1 = sb + SM_A1;
        #pragma unroll
        for (int rk = 0; rk < 8; ++rk) {
            asm volatile("mapa.shared::cluster.u32 %0, %1, %2;" : "=r"(ra0[rk]) : "r"(a0), "r"(rk));
            asm volatile("mapa.shared::cluster.u32 %0, %1, %2;" : "=r"(ra1[rk]) : "r"(a1), "r"(rk));
        }
    }

    // thread/cell geometry (R9-proven)
    const int d_    = (lane & 3) >> 1;
    const bool isT0 = ((lane & 1) == 0);
    const int r1    = lane >> 2;
    const int myrow = r1 + ((lane & 1) << 3);
    const int q0    = (lane & 1) ? 2 : 0;

    float c[4], hp[4];
    int lcs[4];
    #pragma unroll
    for (int s = 0; s < 4; ++s) {
        lcs[s] = 8 * w + 2 * s + d_;
        c[s]  = cxs[(size_t)(b0 + myrow) * Hc + u0 + lcs[s]];
        hp[s] = 0.0f;
    }
    float ar = 0.0f, tar = 0.0f;

    const uint32_t aoff = (uint32_t)((lane & 7) + ((lane >> 3) & 1) * 8) * 528
                        + (uint32_t)((lane >> 4) & 1) * 16;
    const uint32_t bofs0 = (uint32_t)(32 * w) * 528 + aoff;
    const uint32_t bofs1 = (uint32_t)(32 * w + 16) * 528 + aoff;

    __half* stage_h = (__half*)(smc + SM_STG);
    __half* stage_l = (__half*)(smc + SM_STG + 1024);

    __syncthreads();

    // prefetch g_pre for t=0
    float pre[4][4];
    {
        size_t p1 = ((size_t)((b0 + r1) * Tc)) * 1024;
        size_t p2 = ((size_t)((b0 + r1 + 8) * Tc)) * 1024;
        #pragma unroll
        for (int s = 0; s < 4; ++s) {
            int col = q0 * 256 + u0 + lcs[s];
            pre[s][0] = g_pre[p1 + col]; pre[s][1] = g_pre[p1 + col + 256];
            pre[s][2] = g_pre[p2 + col]; pre[s][3] = g_pre[p2 + col + 256];
        }
    }

    int cur = 0;
    for (int t = 0; t < Tc; ++t) {
        float acc[4][4];
        #pragma unroll
        for (int s = 0; s < 4; ++s) {
            acc[s][0] = pre[s][0]; acc[s][1] = pre[s][1];
            acc[s][2] = pre[s][2]; acc[s][3] = pre[s][3];
        }

        const uint32_t abh = sb + (cur ? SM_A1 : SM_A0);
        const uint32_t abl = abh + ABUF / 2;

        #pragma unroll 4
        for (int kc = 0; kc < 16; ++kc) {
            const uint32_t ko = (uint32_t)kc * 32;
            uint32_t ah[4], al[4], p0h[4], p1h[4];
            ldsm4(ah, abh + aoff + ko);
            ldsm4(al, abl + aoff + ko);
            ldsm4(p0h, sb + SM_BH + bofs0 + ko);
            ldsm4(p1h, sb + SM_BH + bofs1 + ko);
            uint32_t bh[4][2] = {{p0h[0], p0h[2]}, {p0h[1], p0h[3]},
                                 {p1h[0], p1h[2]}, {p1h[1], p1h[3]}};
            #pragma unroll
            for (int s = 0; s < 4; ++s) {
                mma16816h(acc[s], ah, bh[s]);
                mma16816h(acc[s], al, bh[s]);
            }
        }

        // pointwise cell (values kept in registers; stores deferred)
        float iv[4], fv[4], gv[4], ov[4], c2a[4], h2a[4];
        #pragma unroll
        for (int s = 0; s < 4; ++s) {
            float sh1 = __shfl_xor_sync(0xffffffffu, isT0 ? acc[s][2] : acc[s][0], 1);
            float sh2 = __shfl_xor_sync(0xffffffffu, isT0 ? acc[s][3] : acc[s][1], 1);
            float i_, f_, g_, o_;
            if (isT0) { i_ = acc[s][0]; f_ = acc[s][1]; g_ = sh1; o_ = sh2; }
            else      { g_ = acc[s][2]; o_ = acc[s][3]; i_ = sh1; f_ = sh2; }

            iv[s] = sigm(i_); fv[s] = sigm(f_); gv[s] = tanh_f(g_); ov[s] = sigm(o_);
            float c2 = fmaf(fv[s], c[s], iv[s] * gv[s]);
            float h2 = ov[s] * tanh_f(c2);
            c2a[s] = c2; h2a[s] = h2;
            c[s] = c2;
            ar = fmaf(h2, h2, ar);
            float dd = h2 - hp[s];
            if (t > 0) tar = fmaf(dd, dd, tar);
            hp[s] = h2;

            __half hh = __float2half_rn(h2);
            stage_h[myrow * 32 + lcs[s]] = hh;
            stage_l[myrow * 32 + lcs[s]] = __float2half_rn(h2 - __half2float(hh));
        }

        __syncthreads();

        // push own 32-unit h chunk (hi+lo planes) to all 8 ranks' next buffer
        {
            const int p   = tid >> 6;
            const int rem = tid & 63;
            const int row = rem >> 2;
            const int ch  = rem & 3;
            uint4 v = *(const uint4*)(smc + SM_STG + p * 1024 + (row * 32 + ch * 8) * 2);
            const uint32_t dsto = (uint32_t)p * (ABUF / 2) + (uint32_t)row * 528
                                + (uint32_t)(u0 + ch * 8) * 2;
            const unsigned* rbuf = cur ? ra0 : ra1;
            #pragma unroll
            for (int rk = 0; rk < 8; ++rk) {
                asm volatile("st.shared::cluster.v4.b32 [%0], {%1,%2,%3,%4};"
                             :: "r"(rbuf[rk] + dsto), "r"(v.x), "r"(v.y), "r"(v.z), "r"(v.w)
                             : "memory");
            }
        }

        asm volatile("barrier.cluster.arrive.aligned;" ::: "memory");

        // hidden inside arrive->wait: gate stores + next-step pre prefetch
        #pragma unroll
        for (int s = 0; s < 4; ++s) {
            const int grow = b0 + myrow;
            const int unit = u0 + lcs[s];
            const size_t base = ((size_t)(grow * Tc + t)) * Hc + unit;
            __stcs(&out[OFF_I  + base], iv[s]);
            __stcs(&out[OFF_Fg + base], fv[s]);
            __stcs(&out[OFF_Gg + base], gv[s]);
            __stcs(&out[OFF_Og + base], ov[s]);
            __stcs(&out[OFF_CS + base], c2a[s]);
            __stcs(&out[OFF_HS + base], h2a[s]);
            if (t == Tc - 1) {
                out[OFF_HT + (size_t)grow * Hc + unit] = h2a[s];
                out[OFF_CT + (size_t)grow * Hc + unit] = c2a[s];
            }
        }
        if (t + 1 < Tc) {
            size_t p1 = ((size_t)((b0 + r1) * Tc + t + 1)) * 1024;
            size_t p2 = ((size_t)((b0 + r1 + 8) * Tc + t + 1)) * 1024;
            #pragma unroll
            for (int s = 0; s < 4; ++s) {
                int col = q0 * 256 + u0 + lcs[s];
                pre[s][0] = g_pre[p1 + col]; pre[s][1] = g_pre[p1 + col + 256];
                pre[s][2] = g_pre[p2 + col]; pre[s][3] = g_pre[p2 + col + 256];
            }
        }

        asm volatile("barrier.cluster.wait.aligned;" ::: "memory");
        cur ^= 1;
    }

    __shared__ float red[128];
    red[tid] = ar; __syncthreads();
    for (int o = 64; o > 0; o >>= 1) { if (tid < o) red[tid] += red[tid + o]; __syncthreads(); }
    if (tid == 0) g_part[blockIdx.x] = red[0];
    __syncthreads();
    red[tid] = tar; __syncthreads();
    for (int o = 64; o > 0; o >>= 1) { if (tid < o) red[tid] += red[tid + o]; __syncthreads(); }
    if (tid == 0) g_part[128 + blockIdx.x] = red[0];
}

// ---------------------------------------------------------------------------
// loss finalize
// ---------------------------------------------------------------------------
__global__ void loss_fin(float* __restrict__ out)
{
    __shared__ float r[128];
    int tid = threadIdx.x;
    r[tid] = g_part[tid]; __syncthreads();
    for (int o = 64; o > 0; o >>= 1) { if (tid < o) r[tid] += r[tid + o]; __syncthreads(); }
    float sar = r[0]; __syncthreads();
    r[tid] = g_part[128 + tid]; __syncthreads();
    for (int o = 64; o > 0; o >>= 1) { if (tid < o) r[tid] += r[tid + o]; __syncthreads(); }
    if (tid == 0) {
        out[OFF_AR]  = sar * (0.01f / 16777216.0f);
        out[OFF_TAR] = r[0] * (0.01f / 16711680.0f);
    }
}

// ---------------------------------------------------------------------------
// actor/critic heads
// ---------------------------------------------------------------------------
__global__ __launch_bounds__(256)
void head_kernel(const float* __restrict__ aw, const float* __restrict__ ab,
                 const float* __restrict__ cw, const float* __restrict__ cb,
                 float* __restrict__ out)
{
    __shared__ float ws[19 * 256];
    const int tid = threadIdx.x;
    for (int i = tid; i < Ac * Hc; i += 256) ws[i] = aw[i];
    for (int i = tid; i < Hc; i += 256) ws[Ac * Hc + i] = cw[i];
    __syncthreads();

    const int warp = tid >> 5, lane = tid & 31;
    const size_t m = (size_t)blockIdx.x * 8 + warp;
    const float* h = &out[OFF_HS + m * Hc];

    float p[19];
    #pragma unroll
    for (int o = 0; o < 19; ++o) p[o] = 0.0f;
    #pragma unroll
    for (int kk = 0; kk < 8; ++kk) {
        int k = lane + kk * 32;
        float hv = h[k];
        #pragma unroll
        for (int o = 0; o < 19; ++o) p[o] = fmaf(hv, ws[o * 256 + k], p[o]);
    }
    #pragma unroll
    for (int o = 0; o < 19; ++o)
        #pragma unroll
        for (int off = 16; off > 0; off >>= 1)
            p[o] += __shfl_down_sync(0xffffffffu, p[o], off);

    if (lane == 0) {
        #pragma unroll
        for (int o = 0; o < Ac; ++o)
            out[OFF_LOGITS + m * Ac + o] = p[o] + ab[o];
        out[OFF_VALUES + m] = p[18] + cb[0];
    }
}

// ---------------------------------------------------------------------------
// launcher
// ---------------------------------------------------------------------------
extern "C" void kernel_launch(void* const* d_in, const int* in_sizes, int n_in,
                              void* d_out, int out_size)
{
    const float* obs    = (const float*)d_in[0];
    const float* hxs    = (const float*)d_in[1];
    const float* cxs    = (const float*)d_in[2];
    const float* enc_w1 = (const float*)d_in[3];
    const float* enc_b1 = (const float*)d_in[4];
    const float* enc_w2 = (const float*)d_in[5];
    const float* enc_b2 = (const float*)d_in[6];
    const float* w_ih   = (const float*)d_in[7];
    const float* w_hh   = (const float*)d_in[8];
    const float* b_ih   = (const float*)d_in[9];
    const float* b_hh   = (const float*)d_in[10];
    const float* aw     = (const float*)d_in[11];
    const float* ab     = (const float*)d_in[12];
    const float* cw     = (const float*)d_in[13];
    const float* cb     = (const float*)d_in[14];
    float* out = (float*)d_out;

    void *p_pre, *p_bias;
    void *p_oh, *p_ol, *p_e1h, *p_e1l, *p_e2h, *p_e2l;
    void *p_w1h, *p_w2h, *p_wihh;
    cudaGetSymbolAddress(&p_pre,  g_pre);
    cudaGetSymbolAddress(&p_bias, g_bias);
    cudaGetSymbolAddress(&p_oh,   g_obs_h);  cudaGetSymbolAddress(&p_ol,   g_obs_l);
    cudaGetSymbolAddress(&p_e1h,  g_e1h);    cudaGetSymbolAddress(&p_e1l,  g_e1l);
    cudaGetSymbolAddress(&p_e2h,  g_e2h);    cudaGetSymbolAddress(&p_e2l,  g_e2l);
    cudaGetSymbolAddress(&p_w1h,  g_w1h);
    cudaGetSymbolAddress(&p_w2h,  g_w2h);
    cudaGetSymbolAddress(&p_wihh, g_wih_h);

    cudaFuncSetAttribute(lstm_kernel,
                         cudaFuncAttributeMaxDynamicSharedMemorySize, LSTM_SMEM);
    cudaFuncSetAttribute(gemm_mma,
                         cudaFuncAttributeMaxDynamicSharedMemorySize, GEMM_SMEM_TOT);

    const int M = Bc * Tc;  // 65536

    {
        int n;
        n = M * Dc;      conv_split_h<<<(n + 255) / 256, 256>>>(obs, (__half*)p_oh, (__half*)p_ol, n);
        n = Ec * Dc;     conv_h<<<(n + 255) / 256, 256>>>(enc_w1, (__half*)p_w1h, n);
        n = Ec * Ec;     conv_h<<<(n + 255) / 256, 256>>>(enc_w2, (__half*)p_w2h, n);
        n = 4 * Hc * Ec; conv_h<<<(n + 255) / 256, 256>>>(w_ih,   (__half*)p_wihh, n);
    }
    prep_bias<<<1, 1024>>>(b_ih, b_hh);

    gemm_mma<<<dim3(M / 128, Ec / 128), 256, GEMM_SMEM_TOT>>>(
        (const __half*)p_oh, (const __half*)p_ol, (const __half*)p_w1h,
        enc_b1, nullptr, (__half*)p_e1h, (__half*)p_e1l, Dc, Ec, 1);
    gemm_mma<<<dim3(M / 128, Ec / 128), 256, GEMM_SMEM_TOT>>>(
        (const __half*)p_e1h, (const __half*)p_e1l, (const __half*)p_w2h,
        enc_b2, nullptr, (__half*)p_e2h, (__half*)p_e2l, Ec, Ec, 1);
    gemm_mma<<<dim3(M / 128, (4 * Hc) / 128), 256, GEMM_SMEM_TOT>>>(
        (const __half*)p_e2h, (const __half*)p_e2l, (const __half*)p_wihh,
        (const float*)p_bias, (float*)p_pre, nullptr, nullptr, Ec, 4 * Hc, 0);

    lstm_kernel<<<128, 128, LSTM_SMEM>>>(hxs, cxs, w_hh, out);
    loss_fin<<<1, 128>>>(out);
    head_kernel<<<M / 8, 256>>>(aw, ab, cw, cb, out);
}